// round 3
// baseline (speedup 1.0000x reference)
#include <cuda_runtime.h>

#define NN 32768

// -------- static scratch (allocation-free rule: __device__ globals) --------
__device__ float g_s_all[(size_t)NN * 448];   // s_all; gated in-place by EPI=2 GEMM
__device__ float g_h[(size_t)NN * 448];       // silu(s_all @ W1)
__device__ float g_gates[(size_t)NN * 576];   // h @ W2[:, :576]

// ======================= K1: prep s_all =======================
// s_all[:, :256] = x[:, :256]
// s_all[:, 256+3g+{0,1,2}] = {a.a, sqrt2*a.b, b.b} * (1/sqrt3)
__global__ void prep_kernel(const float* __restrict__ x) {
    const float ISQ3 = 0.57735026918962576f;
    const float SQ2  = 1.41421356237309505f;
    int tid = blockIdx.x * blockDim.x + threadIdx.x;
    int stride = gridDim.x * blockDim.x;
    for (int idx = tid; idx < NN * 64; idx += stride) {
        int n = idx >> 6;
        int q4 = idx & 63;
        // copy 256 scalars as float4: q4 0..63 covers 256 floats
        *(float4*)(g_s_all + (size_t)n * 448 + q4 * 4) =
            *(const float4*)(x + (size_t)n * 640 + q4 * 4);
    }
    for (int idx = tid; idx < NN * 64; idx += stride) {
        int n = idx >> 6;
        int g = idx & 63;
        const float* p = x + (size_t)n * 640 + 256 + 6 * g;
        float ax = p[0], ay = p[1], az = p[2];
        float bx = p[3], by = p[4], bz = p[5];
        float aa = ax*ax + ay*ay + az*az;
        float ab = ax*bx + ay*by + az*bz;
        float bb = bx*bx + by*by + bz*bz;
        float* q = g_s_all + (size_t)n * 448 + 256 + 3 * g;
        q[0] = aa * ISQ3;
        q[1] = SQ2 * ab * ISQ3;
        q[2] = bb * ISQ3;
    }
}

// ======================= SGEMM =======================
// C[M,N] = epi( A[M,K] @ B[K,N] * scale ), row-major, tiles BM=128 BN=64 BK=16
// 256 threads, 8x4 per-thread microtile.
// EPI: 0 = none, 1 = silu, 2 = also gate S in place for columns < 448.
template <int EPI>
__global__ void __launch_bounds__(256)
sgemm_kernel(const float* __restrict__ A, const float* __restrict__ B,
             float* __restrict__ C, int K, int lda, int ldb, int ldc,
             float scale, float* __restrict__ S, int lds) {
    __shared__ float As[16][132];   // [k][m], padded
    __shared__ float Bs[16][64];    // [k][n]

    const int tid = threadIdx.x;
    const int tx = tid & 15;        // n-dir (16 * 4 = 64)
    const int ty = tid >> 4;        // m-dir (16 * 8 = 128)
    const int bn = blockIdx.x * 64;
    const int bm = blockIdx.y * 128;

    const int arow = tid >> 2;      // 0..63
    const int akq  = tid & 3;       // 0..3 (k quarter, 4 floats each)
    const int brow = tid >> 4;      // 0..15
    const int bc4  = tid & 15;      // 0..15

    float acc[8][4];
#pragma unroll
    for (int i = 0; i < 8; i++)
#pragma unroll
        for (int j = 0; j < 4; j++) acc[i][j] = 0.f;

    for (int kt = 0; kt < K; kt += 16) {
        float4 av0 = *(const float4*)(A + (size_t)(bm + arow) * lda + kt + akq * 4);
        float4 av1 = *(const float4*)(A + (size_t)(bm + arow + 64) * lda + kt + akq * 4);
        float4 bv  = *(const float4*)(B + (size_t)(kt + brow) * ldb + bn + bc4 * 4);
        As[akq * 4 + 0][arow] = av0.x;
        As[akq * 4 + 1][arow] = av0.y;
        As[akq * 4 + 2][arow] = av0.z;
        As[akq * 4 + 3][arow] = av0.w;
        As[akq * 4 + 0][arow + 64] = av1.x;
        As[akq * 4 + 1][arow + 64] = av1.y;
        As[akq * 4 + 2][arow + 64] = av1.z;
        As[akq * 4 + 3][arow + 64] = av1.w;
        *(float4*)&Bs[brow][bc4 * 4] = bv;
        __syncthreads();

#pragma unroll
        for (int kk = 0; kk < 16; kk++) {
            const float4 A0 = *(const float4*)&As[kk][ty * 8];
            const float4 A1 = *(const float4*)&As[kk][ty * 8 + 4];
            const float4 Bv = *(const float4*)&Bs[kk][tx * 4];
            float a[8] = {A0.x, A0.y, A0.z, A0.w, A1.x, A1.y, A1.z, A1.w};
            float b[4] = {Bv.x, Bv.y, Bv.z, Bv.w};
#pragma unroll
            for (int i = 0; i < 8; i++)
#pragma unroll
                for (int j = 0; j < 4; j++)
                    acc[i][j] = fmaf(a[i], b[j], acc[i][j]);
        }
        __syncthreads();
    }

    const bool gate_cols = (EPI == 2) && (bn < 448);
#pragma unroll
    for (int i = 0; i < 8; i++) {
        size_t row = (size_t)(bm + ty * 8 + i);
        float4 c;
        c.x = acc[i][0] * scale;
        c.y = acc[i][1] * scale;
        c.z = acc[i][2] * scale;
        c.w = acc[i][3] * scale;
        if (EPI == 1) {
            c.x = c.x / (1.f + expf(-c.x));
            c.y = c.y / (1.f + expf(-c.y));
            c.z = c.z / (1.f + expf(-c.z));
            c.w = c.w / (1.f + expf(-c.w));
        }
        *(float4*)(C + row * ldc + bn + tx * 4) = c;
        if (gate_cols) {
            float4* sp = (float4*)(S + row * lds + bn + tx * 4);
            float4 sv = *sp;
            sv.x *= c.x; sv.y *= c.y; sv.z *= c.z; sv.w *= c.w;
            *sp = sv;
        }
    }
}

// ======================= K4: o1 + RMS =======================
// Per node: o1[k,i] = sum_m v[m,i]*g1o[m]*Wl1[m,k]/sqrt(128);
// RMS-normalize o1 over all 384 values; write to out[:, 256:640].
// 256 threads handle 2 nodes at a time (128 threads = one node, thread = k).
__global__ void __launch_bounds__(256)
gate_o1_kernel(const float* __restrict__ x, const float* __restrict__ Wl1,
               float* __restrict__ out) {
    extern __shared__ float sm[];
    float* Wt  = sm;                  // [k][m] transposed Wl1, row stride 129
    float* v1s = sm + 128 * 129;      // 2 nodes x 384 (16B-aligned)
    float* ssq = v1s + 768;           // 8 per-warp partials

    const int tid = threadIdx.x;
    for (int idx = tid; idx < 128 * 128; idx += 256) {
        int m = idx >> 7;
        int k = idx & 127;
        Wt[k * 129 + m] = Wl1[idx];
    }

    const int ln = tid >> 7;        // 0/1 : which node of the pair
    const int k  = tid & 127;
    const int wn = (tid >> 5) & 3;  // warp within node
    const int base = blockIdx.x * 16;

    for (int p = 0; p < 8; p++) {
        __syncthreads();            // Wt ready (iter 0) / v1s free (iters >0)
        const int n0 = base + p * 2;

        // v1o into smem: 2 x 384  (v * g1o)
        for (int idx = tid; idx < 768; idx += 256) {
            int hi = (idx >= 384);
            int r  = idx - hi * 384;
            int m  = r / 3;
            v1s[idx] = x[(size_t)(n0 + hi) * 640 + 256 + r] *
                       g_gates[(size_t)(n0 + hi) * 576 + 448 + m];
        }
        if (tid < 8) ssq[tid] = 0.f;
        __syncthreads();

        const float* v = v1s + ln * 384;
        float a0 = 0.f, a1 = 0.f, a2 = 0.f;
#pragma unroll
        for (int m4 = 0; m4 < 32; m4++) {
            float w0 = Wt[k * 129 + 4 * m4 + 0];
            float w1 = Wt[k * 129 + 4 * m4 + 1];
            float w2 = Wt[k * 129 + 4 * m4 + 2];
            float w3 = Wt[k * 129 + 4 * m4 + 3];
            float4 va = *(const float4*)&v[m4 * 12];
            float4 vb = *(const float4*)&v[m4 * 12 + 4];
            float4 vc = *(const float4*)&v[m4 * 12 + 8];
            a0 = fmaf(va.x, w0, fmaf(va.w, w1, fmaf(vb.z, w2, fmaf(vc.y, w3, a0))));
            a1 = fmaf(va.y, w0, fmaf(vb.x, w1, fmaf(vb.w, w2, fmaf(vc.z, w3, a1))));
            a2 = fmaf(va.z, w0, fmaf(vb.y, w1, fmaf(vc.x, w2, fmaf(vc.w, w3, a2))));
        }
        const float sc = 0.08838834764831845f;  // 1/sqrt(128)
        a0 *= sc; a1 *= sc; a2 *= sc;
        float q = a0 * a0 + a1 * a1 + a2 * a2;
#pragma unroll
        for (int o = 16; o; o >>= 1) q += __shfl_xor_sync(0xffffffffu, q, o);
        if ((tid & 31) == 0) ssq[ln * 4 + wn] = q;
        __syncthreads();
        float tot = ssq[ln * 4] + ssq[ln * 4 + 1] + ssq[ln * 4 + 2] + ssq[ln * 4 + 3];
        float r = rsqrtf(tot * (1.f / 384.f) + 1e-6f);
        size_t ob = (size_t)(n0 + ln) * 640 + 256 + 3 * k;
        out[ob]     = a0 * r;
        out[ob + 1] = a1 * r;
        out[ob + 2] = a2 * r;
    }
}

// ======================= K6: LayerNorm over out[:, :256] =======================
__global__ void lnorm_kernel(float* __restrict__ out) {
    int n = blockIdx.x * blockDim.y + threadIdx.y;
    float* row = out + (size_t)n * 640;
    int lane = threadIdx.x;
    float v[8];
    float s = 0.f;
#pragma unroll
    for (int j = 0; j < 8; j++) {
        v[j] = row[lane + 32 * j];
        s += v[j];
    }
#pragma unroll
    for (int o = 16; o; o >>= 1) s += __shfl_xor_sync(0xffffffffu, s, o);
    float mu = s * (1.f / 256.f);
    float q = 0.f;
#pragma unroll
    for (int j = 0; j < 8; j++) {
        float d = v[j] - mu;
        q = fmaf(d, d, q);
    }
#pragma unroll
    for (int o = 16; o; o >>= 1) q += __shfl_xor_sync(0xffffffffu, q, o);
    float r = rsqrtf(q * (1.f / 256.f) + 1e-6f);
#pragma unroll
    for (int j = 0; j < 8; j++) row[lane + 32 * j] = (v[j] - mu) * r;
}

// ======================= launch =======================
extern "C" void kernel_launch(void* const* d_in, const int* in_sizes, int n_in,
                              void* d_out, int out_size) {
    const float* x   = (const float*)d_in[0];   // [32768, 640]
    const float* W1  = (const float*)d_in[1];   // [448, 448]
    const float* W2  = (const float*)d_in[2];   // [448, 832] (use first 576 cols)
    const float* Wl0 = (const float*)d_in[3];   // [448, 256]
    const float* Wl1 = (const float*)d_in[4];   // [128, 128]
    float* out = (float*)d_out;                 // [32768, 640]

    float *s_all, *h, *gates;
    cudaGetSymbolAddress((void**)&s_all, g_s_all);
    cudaGetSymbolAddress((void**)&h, g_h);
    cudaGetSymbolAddress((void**)&gates, g_gates);

    const float inv_fan = 0.04724555652982141f;  // 1/sqrt(448)

    prep_kernel<<<2048, 256>>>(x);

    // h = silu(s_all @ W1 / sqrt(448))
    sgemm_kernel<1><<<dim3(448 / 64, NN / 128), 256>>>(
        s_all, W1, h, 448, 448, 448, 448, inv_fan, nullptr, 0);

    // gates = h @ W2[:, :576] / sqrt(448); also s_all *= gates[:, :448] in place
    sgemm_kernel<2><<<dim3(576 / 64, NN / 128), 256>>>(
        h, W2, gates, 448, 448, 832, 576, inv_fan, s_all, 448);

    // o1 + RMS -> out[:, 256:640]
    int go_smem = (128 * 129 + 768 + 8) * 4;  // 69152 bytes
    cudaFuncSetAttribute(gate_o1_kernel,
                         cudaFuncAttributeMaxDynamicSharedMemorySize, go_smem);
    gate_o1_kernel<<<NN / 16, 256, go_smem>>>(x, Wl1, out);

    // o0_pre = s_gated @ Wl0 / sqrt(448) -> out[:, :256] (ldc = 640)
    sgemm_kernel<0><<<dim3(256 / 64, NN / 128), 256>>>(
        s_all, Wl0, out, 448, 448, 256, 640, inv_fan, nullptr, 0);

    // LayerNorm over out[:, :256]
    lnorm_kernel<<<NN / 8, dim3(32, 8)>>>(out);
}

// round 8
// speedup vs baseline: 1.5278x; 1.5278x over previous
#include <cuda_runtime.h>
#include <cuda_bf16.h>
#include <cstdint>

#define NN 32768
typedef __nv_bfloat16 bf16;

// ======================= static scratch (__device__ globals) =======================
// hi/lo layout: row has 896 bf16 = [hi(448) | lo(448)]
__device__ __align__(16) bf16 g_s [(size_t)NN * 896];
__device__ __align__(16) bf16 g_h [(size_t)NN * 896];
__device__ __align__(16) bf16 g_sg[(size_t)NN * 896];
__device__ __align__(16) float g_g1o[(size_t)NN * 128];
__device__ __align__(16) bf16 g_w1 [448 * 896];   // B1[n][k'] = W1 [k][n] split
__device__ __align__(16) bf16 g_w2 [576 * 896];   // B2[n][k'] = W2 [k][n] split
__device__ __align__(16) bf16 g_wl0[256 * 896];   // B3[n][k'] = Wl0[k][n] split

__device__ __forceinline__ void split2(float v, bf16* hi, bf16* lo) {
    bf16 h = __float2bfloat16(v);
    *hi = h;
    *lo = __float2bfloat16(v - __bfloat162float(h));
}

__device__ __forceinline__ uint32_t smem_u32(const void* p) {
    uint32_t a;
    asm("{ .reg .u64 t; cvta.to.shared.u64 t, %1; cvt.u32.u64 %0, t; }" : "=r"(a) : "l"(p));
    return a;
}

#define CP_ASYNC16(dst_u32, src_ptr) \
    asm volatile("cp.async.cg.shared.global [%0], [%1], 16;" \
                 :: "r"(dst_u32), "l"(src_ptr) : "memory")
#define CP_COMMIT()  asm volatile("cp.async.commit_group;" ::: "memory")
#define CP_WAIT1()   asm volatile("cp.async.wait_group 1;" ::: "memory")
#define CP_WAIT0()   asm volatile("cp.async.wait_group 0;" ::: "memory")

#define LDM4(r, addr) \
    asm volatile("ldmatrix.sync.aligned.m8n8.x4.shared.b16 {%0,%1,%2,%3}, [%4];" \
        : "=r"((r)[0]), "=r"((r)[1]), "=r"((r)[2]), "=r"((r)[3]) : "r"(addr))

#define MMA16816(d, a, b0r, b1r) \
    asm volatile("mma.sync.aligned.m16n8k16.row.col.f32.bf16.bf16.f32 " \
        "{%0,%1,%2,%3}, {%4,%5,%6,%7}, {%8,%9}, {%0,%1,%2,%3};" \
        : "+f"((d)[0]), "+f"((d)[1]), "+f"((d)[2]), "+f"((d)[3]) \
        : "r"((a)[0]), "r"((a)[1]), "r"((a)[2]), "r"((a)[3]), "r"(b0r), "r"(b1r))

// ======================= prep: x -> s' (hi|lo, 896) =======================
__global__ void prep_split_kernel(const float* __restrict__ x) {
    const float ISQ3 = 0.57735026918962576f;
    const float SQ2  = 1.41421356237309505f;
    int n = blockIdx.x;
    int j = threadIdx.x;
    float val;
    if (j < 256) {
        val = x[(size_t)n * 640 + j];
    } else {
        int jj = j - 256;
        int g = jj / 3;
        int i = jj - 3 * g;
        const float* p = x + (size_t)n * 640 + 256 + 6 * g;
        float ax = p[0], ay = p[1], az = p[2];
        float bx = p[3], by = p[4], bz = p[5];
        if (i == 0)      val = (ax*ax + ay*ay + az*az) * ISQ3;
        else if (i == 1) val = SQ2 * (ax*bx + ay*by + az*bz) * ISQ3;
        else             val = (bx*bx + by*by + bz*bz) * ISQ3;
    }
    size_t o = (size_t)n * 896 + j;
    split2(val, &g_s[o], &g_s[o + 448]);
}

// ======================= prep: transpose + split weights =======================
__global__ void prep_w_kernel(const float* __restrict__ W1,
                              const float* __restrict__ W2,
                              const float* __restrict__ Wl0) {
    int idx = blockIdx.x * blockDim.x + threadIdx.x;
    int stride = gridDim.x * blockDim.x;
    const int T1 = 448 * 448, T2 = T1 + 576 * 448, T3 = T2 + 256 * 448;
    for (; idx < T3; idx += stride) {
        if (idx < T1) {
            int n = idx / 448, k = idx - n * 448;
            size_t o = (size_t)n * 896 + k;
            split2(W1[(size_t)k * 448 + n], &g_w1[o], &g_w1[o + 448]);
        } else if (idx < T2) {
            int i = idx - T1;
            int n = i / 448, k = i - n * 448;
            size_t o = (size_t)n * 896 + k;
            split2(W2[(size_t)k * 832 + n], &g_w2[o], &g_w2[o + 448]);
        } else {
            int i = idx - T2;
            int n = i / 448, k = i - n * 448;
            size_t o = (size_t)n * 896 + k;
            split2(Wl0[(size_t)k * 256 + n], &g_wl0[o], &g_wl0[o + 448]);
        }
    }
}

// ======================= mma.sync bf16 GEMM (TN, split-K' = 1344) =======================
// C = (Ah Bh^T + Al Bh^T + Ah Bl^T) * scale, fp32 accum.
// Logical K' = 1344 = 42 chunks of 32; chunk c maps:
//   c in [0,14):  A<-hi  B<-hi ;  c in [14,28): A<-lo  B<-hi ;  c in [28,42): A<-hi B<-lo
// Block 128x64, 8 warps (warp tile 32x32), cp.async double-buffered.
// EPI: 0 = write fp32 to outf (ld 640); 1 = silu -> oh (hi|lo);
//      2 = col<448: sg = s*(gate) -> oh ; col>=448: g1o fp32 -> outf (ld 128).
template <int EPI>
__global__ void __launch_bounds__(256)
mma_gemm(const bf16* __restrict__ A, const bf16* __restrict__ B,
         float scale, float* __restrict__ outf, bf16* __restrict__ oh,
         const bf16* __restrict__ sin_) {
    constexpr int STG = 15360;               // 128*80 + 64*80
    __shared__ __align__(16) char smem[2 * STG];
    const uint32_t sb = smem_u32(smem);

    const int tid  = threadIdx.x;
    const int lane = tid & 31;
    const int wid  = tid >> 5;
    const int wm   = wid >> 1;               // 0..3
    const int wn   = wid & 1;                // 0..1
    const int bm   = blockIdx.y * 128;
    const int bn   = blockIdx.x * 64;

    const int ar0 = tid >> 2, aq = tid & 3;
    const int br0 = tid >> 2;

    float acc[2][4][4];
#pragma unroll
    for (int i = 0; i < 2; i++)
#pragma unroll
        for (int j = 0; j < 4; j++)
#pragma unroll
            for (int l = 0; l < 4; l++) acc[i][j][l] = 0.f;

    const int lrow  = lane & 15;
    const int lkoff = (lane >> 4) * 8;
    const uint32_t a_off = (uint32_t)((wm * 32 + lrow) * 80 + lkoff * 2);
    const uint32_t b_off = (uint32_t)(128 * 80 + (wn * 32 + lrow) * 80 + lkoff * 2);

    auto issue = [&](int c) {
        // chunk -> K offsets in the 896-wide hi|lo buffers
        int ak, bk;
        if (c < 14)      { ak = c * 32;              bk = c * 32; }
        else if (c < 28) { ak = 448 + (c - 14) * 32; bk = (c - 14) * 32; }
        else             { ak = (c - 28) * 32;       bk = 448 + (c - 28) * 32; }
        const int s = c & 1;
        const uint32_t base = sb + s * STG;
        {
            const bf16* src = A + (size_t)(bm + ar0) * 896 + ak + aq * 8;
            CP_ASYNC16(base + ar0 * 80 + aq * 16, src);
            const bf16* src2 = A + (size_t)(bm + ar0 + 64) * 896 + ak + aq * 8;
            CP_ASYNC16(base + (ar0 + 64) * 80 + aq * 16, src2);
        }
        {
            const bf16* src = B + (size_t)(bn + br0) * 896 + bk + aq * 8;
            CP_ASYNC16(base + 128 * 80 + br0 * 80 + aq * 16, src);
        }
        CP_COMMIT();
    };

    issue(0);
    for (int kt = 0; kt < 42; kt++) {
        if (kt + 1 < 42) { issue(kt + 1); CP_WAIT1(); }
        else             { CP_WAIT0(); }
        __syncthreads();

        const uint32_t base = sb + (kt & 1) * STG;
#pragma unroll
        for (int ks = 0; ks < 2; ks++) {
            uint32_t a0[4], a1[4], b0[4], b1[4];
            LDM4(a0, base + a_off + ks * 32);
            LDM4(a1, base + a_off + 16 * 80 + ks * 32);
            LDM4(b0, base + b_off + ks * 32);
            LDM4(b1, base + b_off + 16 * 80 + ks * 32);
            MMA16816(acc[0][0], a0, b0[0], b0[2]);
            MMA16816(acc[0][1], a0, b0[1], b0[3]);
            MMA16816(acc[0][2], a0, b1[0], b1[2]);
            MMA16816(acc[0][3], a0, b1[1], b1[3]);
            MMA16816(acc[1][0], a1, b0[0], b0[2]);
            MMA16816(acc[1][1], a1, b0[1], b0[3]);
            MMA16816(acc[1][2], a1, b1[0], b1[2]);
            MMA16816(acc[1][3], a1, b1[1], b1[3]);
        }
        __syncthreads();
    }

    // ---- epilogue ----
    const int crow = lane >> 2;
    const int ccol = (lane & 3) * 2;
#pragma unroll
    for (int mf = 0; mf < 2; mf++) {
#pragma unroll
        for (int noct = 0; noct < 4; noct++) {
            const int gn = bn + wn * 32 + noct * 8 + ccol;
#pragma unroll
            for (int half = 0; half < 2; half++) {
                const int gm = bm + wm * 32 + mf * 16 + crow + half * 8;
                float v0 = acc[mf][noct][half * 2]     * scale;
                float v1 = acc[mf][noct][half * 2 + 1] * scale;
                if (EPI == 0) {
                    *(float2*)&outf[(size_t)gm * 640 + gn] = make_float2(v0, v1);
                } else if (EPI == 1) {
                    v0 = v0 / (1.f + expf(-v0));
                    v1 = v1 / (1.f + expf(-v1));
                    size_t o = (size_t)gm * 896 + gn;
                    bf16 h0, l0, h1, l1;
                    split2(v0, &h0, &l0);
                    split2(v1, &h1, &l1);
                    *(__nv_bfloat162*)&oh[o] = __nv_bfloat162(h0, h1);
                    *(__nv_bfloat162*)&oh[o + 448] = __nv_bfloat162(l0, l1);
                } else {
                    if (gn < 448) {
                        size_t o = (size_t)gm * 896 + gn;
                        __nv_bfloat162 sh = *(const __nv_bfloat162*)&sin_[o];
                        __nv_bfloat162 sl = *(const __nv_bfloat162*)&sin_[o + 448];
                        float s0 = __bfloat162float(sh.x) + __bfloat162float(sl.x);
                        float s1 = __bfloat162float(sh.y) + __bfloat162float(sl.y);
                        bf16 h0, l0, h1, l1;
                        split2(s0 * v0, &h0, &l0);
                        split2(s1 * v1, &h1, &l1);
                        *(__nv_bfloat162*)&oh[o] = __nv_bfloat162(h0, h1);
                        *(__nv_bfloat162*)&oh[o + 448] = __nv_bfloat162(l0, l1);
                    } else {
                        *(float2*)&outf[(size_t)gm * 128 + gn - 448] = make_float2(v0, v1);
                    }
                }
            }
        }
    }
}

// ======================= o1 + RMS (4-node unrolled) =======================
__global__ void __launch_bounds__(256)
gate_o1_kernel(const float* __restrict__ x, const float* __restrict__ Wl1,
               const float* __restrict__ g1o, float* __restrict__ out) {
    extern __shared__ float sm[];
    float* Wt  = sm;                    // [128][129]
    float* v1s = sm + 128 * 129;        // 8 nodes x 384
    float* ssq = v1s + 8 * 384;         // 8 nodes x 4 warps

    const int tid = threadIdx.x;
    for (int idx = tid; idx < 128 * 128; idx += 256) {
        int m = idx >> 7, k = idx & 127;
        Wt[k * 129 + m] = Wl1[idx];
    }
    const int h  = tid >> 7;
    const int k  = tid & 127;
    const int w4 = (tid >> 5) & 3;
    const int base = blockIdx.x * 32;
    const float sc = 0.08838834764831845f;  // 1/sqrt(128)

    for (int p = 0; p < 4; p++) {
        __syncthreads();
        const int n0 = base + p * 8;
        for (int idx = tid; idx < 8 * 384; idx += 256) {
            int j = idx / 384;
            int r = idx - j * 384;
            int m = r / 3;
            v1s[idx] = x[(size_t)(n0 + j) * 640 + 256 + r] *
                       g1o[(size_t)(n0 + j) * 128 + m];
        }
        __syncthreads();

        const float* vb = v1s + h * 4 * 384;
        float acc[4][3];
#pragma unroll
        for (int j = 0; j < 4; j++) { acc[j][0] = acc[j][1] = acc[j][2] = 0.f; }
#pragma unroll
        for (int m4 = 0; m4 < 32; m4++) {
            float w0 = Wt[k * 129 + 4 * m4 + 0];
            float w1 = Wt[k * 129 + 4 * m4 + 1];
            float w2 = Wt[k * 129 + 4 * m4 + 2];
            float w3 = Wt[k * 129 + 4 * m4 + 3];
#pragma unroll
            for (int j = 0; j < 4; j++) {
                const float* v = vb + j * 384 + m4 * 12;
                float4 va = *(const float4*)(v);
                float4 vm = *(const float4*)(v + 4);
                float4 vc = *(const float4*)(v + 8);
                acc[j][0] = fmaf(va.x, w0, fmaf(va.w, w1, fmaf(vm.z, w2, fmaf(vc.y, w3, acc[j][0]))));
                acc[j][1] = fmaf(va.y, w0, fmaf(vm.x, w1, fmaf(vm.w, w2, fmaf(vc.z, w3, acc[j][1]))));
                acc[j][2] = fmaf(va.z, w0, fmaf(vm.y, w1, fmaf(vc.x, w2, fmaf(vc.w, w3, acc[j][2]))));
            }
        }
#pragma unroll
        for (int j = 0; j < 4; j++) {
            acc[j][0] *= sc; acc[j][1] *= sc; acc[j][2] *= sc;
            float q = acc[j][0]*acc[j][0] + acc[j][1]*acc[j][1] + acc[j][2]*acc[j][2];
#pragma unroll
            for (int o = 16; o; o >>= 1) q += __shfl_xor_sync(0xffffffffu, q, o);
            if ((tid & 31) == 0) ssq[(h * 4 + j) * 4 + w4] = q;
        }
        __syncthreads();
#pragma unroll
        for (int j = 0; j < 4; j++) {
            int nj = h * 4 + j;
            float tot = ssq[nj * 4] + ssq[nj * 4 + 1] + ssq[nj * 4 + 2] + ssq[nj * 4 + 3];
            float rr = rsqrtf(tot * (1.f / 384.f) + 1e-6f);
            size_t ob = (size_t)(n0 + nj) * 640 + 256 + 3 * k;
            out[ob]     = acc[j][0] * rr;
            out[ob + 1] = acc[j][1] * rr;
            out[ob + 2] = acc[j][2] * rr;
        }
    }
}

// ======================= LayerNorm over out[:, :256] =======================
__global__ void lnorm_kernel(float* __restrict__ out) {
    int n = blockIdx.x * blockDim.y + threadIdx.y;
    float* row = out + (size_t)n * 640;
    int lane = threadIdx.x;
    float v[8];
    float s = 0.f;
#pragma unroll
    for (int j = 0; j < 8; j++) { v[j] = row[lane + 32 * j]; s += v[j]; }
#pragma unroll
    for (int o = 16; o; o >>= 1) s += __shfl_xor_sync(0xffffffffu, s, o);
    float mu = s * (1.f / 256.f);
    float q = 0.f;
#pragma unroll
    for (int j = 0; j < 8; j++) { float d = v[j] - mu; q = fmaf(d, d, q); }
#pragma unroll
    for (int o = 16; o; o >>= 1) q += __shfl_xor_sync(0xffffffffu, q, o);
    float r = rsqrtf(q * (1.f / 256.f) + 1e-6f);
#pragma unroll
    for (int j = 0; j < 8; j++) row[lane + 32 * j] = (v[j] - mu) * r;
}

// ======================= launch =======================
extern "C" void kernel_launch(void* const* d_in, const int* in_sizes, int n_in,
                              void* d_out, int out_size) {
    const float* x   = (const float*)d_in[0];   // [32768, 640]
    const float* W1  = (const float*)d_in[1];   // [448, 448]
    const float* W2  = (const float*)d_in[2];   // [448, 832]
    const float* Wl0 = (const float*)d_in[3];   // [448, 256]
    const float* Wl1 = (const float*)d_in[4];   // [128, 128]
    float* out = (float*)d_out;                 // [32768, 640]

    bf16 *s, *h, *sg, *w1, *w2, *wl0;
    float* g1o;
    cudaGetSymbolAddress((void**)&s,   g_s);
    cudaGetSymbolAddress((void**)&h,   g_h);
    cudaGetSymbolAddress((void**)&sg,  g_sg);
    cudaGetSymbolAddress((void**)&g1o, g_g1o);
    cudaGetSymbolAddress((void**)&w1,  g_w1);
    cudaGetSymbolAddress((void**)&w2,  g_w2);
    cudaGetSymbolAddress((void**)&wl0, g_wl0);

    const float inv_fan = 0.04724555652982141f;  // 1/sqrt(448)

    prep_split_kernel<<<NN, 448>>>(x);
    prep_w_kernel<<<560, 256>>>(W1, W2, Wl0);

    // GEMM1: h = silu(s @ W1 / sqrt(448))   [N=448]
    mma_gemm<1><<<dim3(7, NN / 128), 256>>>(s, w1, inv_fan, nullptr, h, nullptr);

    // GEMM2: gates; cols<448 -> sg = s*gate, cols>=448 -> g1o   [N=576]
    mma_gemm<2><<<dim3(9, NN / 128), 256>>>(h, w2, inv_fan, g1o, sg, s);

    // o1 + RMS -> out[:, 256:640]
    int go_smem = (128 * 129 + 8 * 384 + 32) * 4;
    cudaFuncSetAttribute(gate_o1_kernel, cudaFuncAttributeMaxDynamicSharedMemorySize, go_smem);
    gate_o1_kernel<<<NN / 32, 256, go_smem>>>(x, Wl1, g1o, out);

    // GEMM3: o0 = sg @ Wl0 / sqrt(448) -> out[:, :256]   [N=256]
    mma_gemm<0><<<dim3(4, NN / 128), 256>>>(sg, wl0, inv_fan, out, nullptr, nullptr);

    // LayerNorm over out[:, :256]
    lnorm_kernel<<<NN / 8, dim3(32, 8)>>>(out);
}

// round 9
// speedup vs baseline: 1.8332x; 1.1999x over previous
#include <cuda_runtime.h>
#include <cuda_fp16.h>
#include <cstdint>

#define NN 32768
typedef __half fp16;

// ======================= static scratch (__device__ globals) =======================
// activations: hi/lo fp16 layout, row = [hi(448) | lo(448)]
__device__ __align__(16) fp16 g_s [(size_t)NN * 896];
__device__ __align__(16) fp16 g_h [(size_t)NN * 896];
__device__ __align__(16) fp16 g_sg[(size_t)NN * 896];
__device__ __align__(16) float g_g1o[(size_t)NN * 128];
// weights: plain fp16, transposed: W'[n][k]
__device__ __align__(16) fp16 g_w1 [448 * 448];
__device__ __align__(16) fp16 g_w2 [576 * 448];
__device__ __align__(16) fp16 g_wl0[256 * 448];

__device__ __forceinline__ void split2h(float v, fp16* hi, fp16* lo) {
    fp16 h = __float2half_rn(v);
    *hi = h;
    *lo = __float2half_rn(v - __half2float(h));
}

__device__ __forceinline__ uint32_t smem_u32(const void* p) {
    uint32_t a;
    asm("{ .reg .u64 t; cvta.to.shared.u64 t, %1; cvt.u32.u64 %0, t; }" : "=r"(a) : "l"(p));
    return a;
}

#define CP_ASYNC16(dst_u32, src_ptr) \
    asm volatile("cp.async.cg.shared.global [%0], [%1], 16;" \
                 :: "r"(dst_u32), "l"(src_ptr) : "memory")
#define CP_COMMIT()  asm volatile("cp.async.commit_group;" ::: "memory")
#define CP_WAIT2()   asm volatile("cp.async.wait_group 2;" ::: "memory")
#define CP_WAIT1()   asm volatile("cp.async.wait_group 1;" ::: "memory")
#define CP_WAIT0()   asm volatile("cp.async.wait_group 0;" ::: "memory")

#define LDM4(r, addr) \
    asm volatile("ldmatrix.sync.aligned.m8n8.x4.shared.b16 {%0,%1,%2,%3}, [%4];" \
        : "=r"((r)[0]), "=r"((r)[1]), "=r"((r)[2]), "=r"((r)[3]) : "r"(addr))

#define MMA16816(d, a, b0r, b1r) \
    asm volatile("mma.sync.aligned.m16n8k16.row.col.f32.f16.f16.f32 " \
        "{%0,%1,%2,%3}, {%4,%5,%6,%7}, {%8,%9}, {%0,%1,%2,%3};" \
        : "+f"((d)[0]), "+f"((d)[1]), "+f"((d)[2]), "+f"((d)[3]) \
        : "r"((a)[0]), "r"((a)[1]), "r"((a)[2]), "r"((a)[3]), "r"(b0r), "r"(b1r))

// ======================= prep: x -> s' (hi|lo, 896) =======================
__global__ void prep_split_kernel(const float* __restrict__ x) {
    const float ISQ3 = 0.57735026918962576f;
    const float SQ2  = 1.41421356237309505f;
    int n = blockIdx.x;
    int j = threadIdx.x;
    float val;
    if (j < 256) {
        val = x[(size_t)n * 640 + j];
    } else {
        int jj = j - 256;
        int g = jj / 3;
        int i = jj - 3 * g;
        const float* p = x + (size_t)n * 640 + 256 + 6 * g;
        float ax = p[0], ay = p[1], az = p[2];
        float bx = p[3], by = p[4], bz = p[5];
        if (i == 0)      val = (ax*ax + ay*ay + az*az) * ISQ3;
        else if (i == 1) val = SQ2 * (ax*bx + ay*by + az*bz) * ISQ3;
        else             val = (bx*bx + by*by + bz*bz) * ISQ3;
    }
    size_t o = (size_t)n * 896 + j;
    split2h(val, &g_s[o], &g_s[o + 448]);
}

// ======================= prep: transpose + quantize weights =======================
__global__ void prep_w_kernel(const float* __restrict__ W1,
                              const float* __restrict__ W2,
                              const float* __restrict__ Wl0) {
    int idx = blockIdx.x * blockDim.x + threadIdx.x;
    int stride = gridDim.x * blockDim.x;
    const int T1 = 448 * 448, T2 = T1 + 576 * 448, T3 = T2 + 256 * 448;
    for (; idx < T3; idx += stride) {
        if (idx < T1) {
            int n = idx / 448, k = idx - n * 448;
            g_w1[idx] = __float2half_rn(W1[(size_t)k * 448 + n]);
        } else if (idx < T2) {
            int i = idx - T1;
            int n = i / 448, k = i - n * 448;
            g_w2[i] = __float2half_rn(W2[(size_t)k * 832 + n]);
        } else {
            int i = idx - T2;
            int n = i / 448, k = i - n * 448;
            g_wl0[i] = __float2half_rn(Wl0[(size_t)k * 256 + n]);
        }
    }
}

// ======================= mma.sync fp16 GEMM (TN, split-K' = 896) =======================
// C = (Ah + Al) @ Bh^T * scale (A-quant corrected; B-quant error ~3e-4 rel, OK).
// K' = 896 = 28 chunks of 32; chunk c: ak = c*32 (A is [hi|lo] 896-wide),
// bk = (c<14 ? c*32 : (c-14)*32) (B is 448-wide, traversed twice, L2-hot).
// Block 128x64, 8 warps (warp tile 32x32), 4-stage cp.async pipeline.
// EPI: 0 = fp32 to outf (ld 640); 1 = silu -> oh (hi|lo);
//      2 = col<448: sg = s*gate -> oh ; col>=448: g1o fp32 -> outf (ld 128).
template <int EPI>
__global__ void __launch_bounds__(256)
mma_gemm(const fp16* __restrict__ A, const fp16* __restrict__ B,
         float scale, float* __restrict__ outf, fp16* __restrict__ oh,
         const fp16* __restrict__ sin_) {
    constexpr int STG = 15360;               // 128*80 + 64*80 bytes per stage
    extern __shared__ __align__(16) char smem[];
    const uint32_t sb = smem_u32(smem);

    const int tid  = threadIdx.x;
    const int lane = tid & 31;
    const int wid  = tid >> 5;
    const int wm   = wid >> 1;               // 0..3
    const int wn   = wid & 1;                // 0..1
    const int bm   = blockIdx.y * 128;
    const int bn   = blockIdx.x * 64;

    const int ar0 = tid >> 2, aq = tid & 3;
    const int br0 = tid >> 2;

    float acc[2][4][4];
#pragma unroll
    for (int i = 0; i < 2; i++)
#pragma unroll
        for (int j = 0; j < 4; j++)
#pragma unroll
            for (int l = 0; l < 4; l++) acc[i][j][l] = 0.f;

    const int lrow  = lane & 15;
    const int lkoff = (lane >> 4) * 8;
    const uint32_t a_off = (uint32_t)((wm * 32 + lrow) * 80 + lkoff * 2);
    const uint32_t b_off = (uint32_t)(128 * 80 + (wn * 32 + lrow) * 80 + lkoff * 2);

    auto issue = [&](int c) {
        const int ak = c * 32;
        const int bk = (c < 14) ? c * 32 : (c - 14) * 32;
        const uint32_t base = sb + (uint32_t)(c & 3) * STG;
        {
            const fp16* src = A + (size_t)(bm + ar0) * 896 + ak + aq * 8;
            CP_ASYNC16(base + ar0 * 80 + aq * 16, src);
            const fp16* src2 = A + (size_t)(bm + ar0 + 64) * 896 + ak + aq * 8;
            CP_ASYNC16(base + (ar0 + 64) * 80 + aq * 16, src2);
        }
        {
            const fp16* src = B + (size_t)(bn + br0) * 448 + bk + aq * 8;
            CP_ASYNC16(base + 128 * 80 + br0 * 80 + aq * 16, src);
        }
        CP_COMMIT();
    };

    issue(0); issue(1); issue(2);
    for (int kt = 0; kt < 28; kt++) {
        if (kt < 26)      CP_WAIT2();
        else if (kt == 26) CP_WAIT1();
        else               CP_WAIT0();
        __syncthreads();

        const uint32_t base = sb + (uint32_t)(kt & 3) * STG;
#pragma unroll
        for (int ks = 0; ks < 2; ks++) {
            uint32_t a0[4], a1[4], b0[4], b1[4];
            LDM4(a0, base + a_off + ks * 32);
            LDM4(a1, base + a_off + 16 * 80 + ks * 32);
            LDM4(b0, base + b_off + ks * 32);
            LDM4(b1, base + b_off + 16 * 80 + ks * 32);
            MMA16816(acc[0][0], a0, b0[0], b0[2]);
            MMA16816(acc[0][1], a0, b0[1], b0[3]);
            MMA16816(acc[0][2], a0, b1[0], b1[2]);
            MMA16816(acc[0][3], a0, b1[1], b1[3]);
            MMA16816(acc[1][0], a1, b0[0], b0[2]);
            MMA16816(acc[1][1], a1, b0[1], b0[3]);
            MMA16816(acc[1][2], a1, b1[0], b1[2]);
            MMA16816(acc[1][3], a1, b1[1], b1[3]);
        }
        __syncthreads();          // all reads of stage kt done
        if (kt + 3 < 28) issue(kt + 3);   // reuses buffer (kt-1)%4 — safe
    }

    // ---- epilogue ----
    const int crow = lane >> 2;
    const int ccol = (lane & 3) * 2;
#pragma unroll
    for (int mf = 0; mf < 2; mf++) {
#pragma unroll
        for (int noct = 0; noct < 4; noct++) {
            const int gn = bn + wn * 32 + noct * 8 + ccol;
#pragma unroll
            for (int half = 0; half < 2; half++) {
                const int gm = bm + wm * 32 + mf * 16 + crow + half * 8;
                float v0 = acc[mf][noct][half * 2]     * scale;
                float v1 = acc[mf][noct][half * 2 + 1] * scale;
                if (EPI == 0) {
                    *(float2*)&outf[(size_t)gm * 640 + gn] = make_float2(v0, v1);
                } else if (EPI == 1) {
                    v0 = v0 / (1.f + expf(-v0));
                    v1 = v1 / (1.f + expf(-v1));
                    size_t o = (size_t)gm * 896 + gn;
                    fp16 h0, l0, h1, l1;
                    split2h(v0, &h0, &l0);
                    split2h(v1, &h1, &l1);
                    *(__half2*)&oh[o] = __half2(h0, h1);
                    *(__half2*)&oh[o + 448] = __half2(l0, l1);
                } else {
                    if (gn < 448) {
                        size_t o = (size_t)gm * 896 + gn;
                        __half2 sh = *(const __half2*)&sin_[o];
                        __half2 sl = *(const __half2*)&sin_[o + 448];
                        float s0 = __half2float(sh.x) + __half2float(sl.x);
                        float s1 = __half2float(sh.y) + __half2float(sl.y);
                        fp16 h0, l0, h1, l1;
                        split2h(s0 * v0, &h0, &l0);
                        split2h(s1 * v1, &h1, &l1);
                        *(__half2*)&oh[o] = __half2(h0, h1);
                        *(__half2*)&oh[o + 448] = __half2(l0, l1);
                    } else {
                        *(float2*)&outf[(size_t)gm * 128 + gn - 448] = make_float2(v0, v1);
                    }
                }
            }
        }
    }
}

// ======================= o1 + RMS (4-node unrolled) =======================
__global__ void __launch_bounds__(256)
gate_o1_kernel(const float* __restrict__ x, const float* __restrict__ Wl1,
               const float* __restrict__ g1o, float* __restrict__ out) {
    extern __shared__ float sm[];
    float* Wt  = sm;                    // [128][129]
    float* v1s = sm + 128 * 129;        // 8 nodes x 384
    float* ssq = v1s + 8 * 384;         // 8 nodes x 4 warps

    const int tid = threadIdx.x;
    for (int idx = tid; idx < 128 * 128; idx += 256) {
        int m = idx >> 7, k = idx & 127;
        Wt[k * 129 + m] = Wl1[idx];
    }
    const int h  = tid >> 7;
    const int k  = tid & 127;
    const int w4 = (tid >> 5) & 3;
    const int base = blockIdx.x * 32;
    const float sc = 0.08838834764831845f;  // 1/sqrt(128)

    for (int p = 0; p < 4; p++) {
        __syncthreads();
        const int n0 = base + p * 8;
        for (int idx = tid; idx < 8 * 384; idx += 256) {
            int j = idx / 384;
            int r = idx - j * 384;
            int m = r / 3;
            v1s[idx] = x[(size_t)(n0 + j) * 640 + 256 + r] *
                       g1o[(size_t)(n0 + j) * 128 + m];
        }
        __syncthreads();

        const float* vb = v1s + h * 4 * 384;
        float acc[4][3];
#pragma unroll
        for (int j = 0; j < 4; j++) { acc[j][0] = acc[j][1] = acc[j][2] = 0.f; }
#pragma unroll
        for (int m4 = 0; m4 < 32; m4++) {
            float w0 = Wt[k * 129 + 4 * m4 + 0];
            float w1 = Wt[k * 129 + 4 * m4 + 1];
            float w2 = Wt[k * 129 + 4 * m4 + 2];
            float w3 = Wt[k * 129 + 4 * m4 + 3];
#pragma unroll
            for (int j = 0; j < 4; j++) {
                const float* v = vb + j * 384 + m4 * 12;
                float4 va = *(const float4*)(v);
                float4 vm = *(const float4*)(v + 4);
                float4 vc = *(const float4*)(v + 8);
                acc[j][0] = fmaf(va.x, w0, fmaf(va.w, w1, fmaf(vm.z, w2, fmaf(vc.y, w3, acc[j][0]))));
                acc[j][1] = fmaf(va.y, w0, fmaf(vm.x, w1, fmaf(vm.w, w2, fmaf(vc.z, w3, acc[j][1]))));
                acc[j][2] = fmaf(va.z, w0, fmaf(vm.y, w1, fmaf(vc.x, w2, fmaf(vc.w, w3, acc[j][2]))));
            }
        }
#pragma unroll
        for (int j = 0; j < 4; j++) {
            acc[j][0] *= sc; acc[j][1] *= sc; acc[j][2] *= sc;
            float q = acc[j][0]*acc[j][0] + acc[j][1]*acc[j][1] + acc[j][2]*acc[j][2];
#pragma unroll
            for (int o = 16; o; o >>= 1) q += __shfl_xor_sync(0xffffffffu, q, o);
            if ((tid & 31) == 0) ssq[(h * 4 + j) * 4 + w4] = q;
        }
        __syncthreads();
#pragma unroll
        for (int j = 0; j < 4; j++) {
            int nj = h * 4 + j;
            float tot = ssq[nj * 4] + ssq[nj * 4 + 1] + ssq[nj * 4 + 2] + ssq[nj * 4 + 3];
            float rr = rsqrtf(tot * (1.f / 384.f) + 1e-6f);
            size_t ob = (size_t)(n0 + nj) * 640 + 256 + 3 * k;
            out[ob]     = acc[j][0] * rr;
            out[ob + 1] = acc[j][1] * rr;
            out[ob + 2] = acc[j][2] * rr;
        }
    }
}

// ======================= LayerNorm over out[:, :256] =======================
__global__ void lnorm_kernel(float* __restrict__ out) {
    int n = blockIdx.x * blockDim.y + threadIdx.y;
    float* row = out + (size_t)n * 640;
    int lane = threadIdx.x;
    float v[8];
    float s = 0.f;
#pragma unroll
    for (int j = 0; j < 8; j++) { v[j] = row[lane + 32 * j]; s += v[j]; }
#pragma unroll
    for (int o = 16; o; o >>= 1) s += __shfl_xor_sync(0xffffffffu, s, o);
    float mu = s * (1.f / 256.f);
    float q = 0.f;
#pragma unroll
    for (int j = 0; j < 8; j++) { float d = v[j] - mu; q = fmaf(d, d, q); }
#pragma unroll
    for (int o = 16; o; o >>= 1) q += __shfl_xor_sync(0xffffffffu, q, o);
    float r = rsqrtf(q * (1.f / 256.f) + 1e-6f);
#pragma unroll
    for (int j = 0; j < 8; j++) row[lane + 32 * j] = (v[j] - mu) * r;
}

// ======================= launch =======================
extern "C" void kernel_launch(void* const* d_in, const int* in_sizes, int n_in,
                              void* d_out, int out_size) {
    const float* x   = (const float*)d_in[0];   // [32768, 640]
    const float* W1  = (const float*)d_in[1];   // [448, 448]
    const float* W2  = (const float*)d_in[2];   // [448, 832]
    const float* Wl0 = (const float*)d_in[3];   // [448, 256]
    const float* Wl1 = (const float*)d_in[4];   // [128, 128]
    float* out = (float*)d_out;                 // [32768, 640]

    fp16 *s, *h, *sg, *w1, *w2, *wl0;
    float* g1o;
    cudaGetSymbolAddress((void**)&s,   g_s);
    cudaGetSymbolAddress((void**)&h,   g_h);
    cudaGetSymbolAddress((void**)&sg,  g_sg);
    cudaGetSymbolAddress((void**)&g1o, g_g1o);
    cudaGetSymbolAddress((void**)&w1,  g_w1);
    cudaGetSymbolAddress((void**)&w2,  g_w2);
    cudaGetSymbolAddress((void**)&wl0, g_wl0);

    const float inv_fan = 0.04724555652982141f;  // 1/sqrt(448)
    const int GEMM_SMEM = 4 * 15360;             // 61440

    cudaFuncSetAttribute(mma_gemm<0>, cudaFuncAttributeMaxDynamicSharedMemorySize, GEMM_SMEM);
    cudaFuncSetAttribute(mma_gemm<1>, cudaFuncAttributeMaxDynamicSharedMemorySize, GEMM_SMEM);
    cudaFuncSetAttribute(mma_gemm<2>, cudaFuncAttributeMaxDynamicSharedMemorySize, GEMM_SMEM);

    prep_split_kernel<<<NN, 448>>>(x);
    prep_w_kernel<<<560, 256>>>(W1, W2, Wl0);

    // GEMM1: h = silu(s @ W1 / sqrt(448))   [N=448]
    mma_gemm<1><<<dim3(7, NN / 128), 256, GEMM_SMEM>>>(s, w1, inv_fan, nullptr, h, nullptr);

    // GEMM2: gates; cols<448 -> sg = s*gate, cols>=448 -> g1o   [N=576]
    mma_gemm<2><<<dim3(9, NN / 128), 256, GEMM_SMEM>>>(h, w2, inv_fan, g1o, sg, s);

    // o1 + RMS -> out[:, 256:640]
    int go_smem = (128 * 129 + 8 * 384 + 32) * 4;
    cudaFuncSetAttribute(gate_o1_kernel, cudaFuncAttributeMaxDynamicSharedMemorySize, go_smem);
    gate_o1_kernel<<<NN / 32, 256, go_smem>>>(x, Wl1, g1o, out);

    // GEMM3: o0 = sg @ Wl0 / sqrt(448) -> out[:, :256]   [N=256]
    mma_gemm<0><<<dim3(4, NN / 128), 256, GEMM_SMEM>>>(sg, wl0, inv_fan, out, nullptr, nullptr);

    // LayerNorm over out[:, :256]
    lnorm_kernel<<<NN / 8, dim3(32, 8)>>>(out);
}

// round 10
// speedup vs baseline: 1.9097x; 1.0418x over previous
#include <cuda_runtime.h>
#include <cuda_fp16.h>
#include <cstdint>

#define NN 32768
typedef __half fp16;

// ======================= static scratch (__device__ globals) =======================
// activations: hi/lo fp16 layout, row = [hi(448) | lo(448)]
__device__ __align__(16) fp16 g_s [(size_t)NN * 896];
__device__ __align__(16) fp16 g_h [(size_t)NN * 896];
__device__ __align__(16) fp16 g_sg[(size_t)NN * 896];
__device__ __align__(16) float g_g1o[(size_t)NN * 128];
// weights: plain fp16, transposed: W'[n][k]
__device__ __align__(16) fp16 g_w1 [448 * 448];
__device__ __align__(16) fp16 g_w2 [576 * 448];
__device__ __align__(16) fp16 g_wl0[256 * 448];

__device__ __forceinline__ void split2h(float v, fp16* hi, fp16* lo) {
    fp16 h = __float2half_rn(v);
    *hi = h;
    *lo = __float2half_rn(v - __half2float(h));
}

__device__ __forceinline__ uint32_t smem_u32(const void* p) {
    uint32_t a;
    asm("{ .reg .u64 t; cvta.to.shared.u64 t, %1; cvt.u32.u64 %0, t; }" : "=r"(a) : "l"(p));
    return a;
}

#define CP_ASYNC16(dst_u32, src_ptr) \
    asm volatile("cp.async.cg.shared.global [%0], [%1], 16;" \
                 :: "r"(dst_u32), "l"(src_ptr) : "memory")
#define CP_COMMIT()  asm volatile("cp.async.commit_group;" ::: "memory")
#define CP_WAIT1()   asm volatile("cp.async.wait_group 1;" ::: "memory")
#define CP_WAIT0()   asm volatile("cp.async.wait_group 0;" ::: "memory")

#define LDM4(r, addr) \
    asm volatile("ldmatrix.sync.aligned.m8n8.x4.shared.b16 {%0,%1,%2,%3}, [%4];" \
        : "=r"((r)[0]), "=r"((r)[1]), "=r"((r)[2]), "=r"((r)[3]) : "r"(addr))

#define MMA16816(d, a, b0r, b1r) \
    asm volatile("mma.sync.aligned.m16n8k16.row.col.f32.f16.f16.f32 " \
        "{%0,%1,%2,%3}, {%4,%5,%6,%7}, {%8,%9}, {%0,%1,%2,%3};" \
        : "+f"((d)[0]), "+f"((d)[1]), "+f"((d)[2]), "+f"((d)[3]) \
        : "r"((a)[0]), "r"((a)[1]), "r"((a)[2]), "r"((a)[3]), "r"(b0r), "r"(b1r))

// ======================= prep: x -> s' (hi|lo, 896) =======================
__global__ void prep_split_kernel(const float* __restrict__ x) {
    const float ISQ3 = 0.57735026918962576f;
    const float SQ2  = 1.41421356237309505f;
    int n = blockIdx.x;
    int j = threadIdx.x;
    float val;
    if (j < 256) {
        val = x[(size_t)n * 640 + j];
    } else {
        int jj = j - 256;
        int g = jj / 3;
        int i = jj - 3 * g;
        const float* p = x + (size_t)n * 640 + 256 + 6 * g;
        float ax = p[0], ay = p[1], az = p[2];
        float bx = p[3], by = p[4], bz = p[5];
        if (i == 0)      val = (ax*ax + ay*ay + az*az) * ISQ3;
        else if (i == 1) val = SQ2 * (ax*bx + ay*by + az*bz) * ISQ3;
        else             val = (bx*bx + by*by + bz*bz) * ISQ3;
    }
    size_t o = (size_t)n * 896 + j;
    split2h(val, &g_s[o], &g_s[o + 448]);
}

// ======================= prep: transpose + quantize weights =======================
__global__ void prep_w_kernel(const float* __restrict__ W1,
                              const float* __restrict__ W2,
                              const float* __restrict__ Wl0) {
    int idx = blockIdx.x * blockDim.x + threadIdx.x;
    int stride = gridDim.x * blockDim.x;
    const int T1 = 448 * 448, T2 = T1 + 576 * 448, T3 = T2 + 256 * 448;
    for (; idx < T3; idx += stride) {
        if (idx < T1) {
            int n = idx / 448, k = idx - n * 448;
            g_w1[idx] = __float2half_rn(W1[(size_t)k * 448 + n]);
        } else if (idx < T2) {
            int i = idx - T1;
            int n = i / 448, k = i - n * 448;
            g_w2[i] = __float2half_rn(W2[(size_t)k * 832 + n]);
        } else {
            int i = idx - T2;
            int n = i / 448, k = i - n * 448;
            g_wl0[i] = __float2half_rn(Wl0[(size_t)k * 256 + n]);
        }
    }
}

// ======================= mma.sync fp16 GEMM (TN, split-K' = 896) =======================
// C = (Ah + Al) @ Bh^T * scale. K' = 896 = 14 chunks of 64.
// chunk c: ak = c*64 (A is [hi|lo] 896-wide), bk = (c<7 ? c : c-7)*64 (B 448-wide, 2 passes).
// Block 128x64, 8 warps (warp tile 32x32), BK=64, 3-stage cp.async, ONE barrier/iter.
// SMEM rows padded to 144B (odd multiple of 16 -> ldmatrix conflict-free).
// EPI: 0 = fp32 to outf (ld 640); 1 = silu -> oh (hi|lo);
//      2 = col<448: sg = s*gate -> oh ; col>=448: g1o fp32 -> outf (ld 128).
template <int EPI>
__global__ void __launch_bounds__(256)
mma_gemm(const fp16* __restrict__ A, const fp16* __restrict__ B,
         float scale, float* __restrict__ outf, fp16* __restrict__ oh,
         const fp16* __restrict__ sin_) {
    constexpr int ROWB = 144;                 // bytes per SMEM row (128 data + 16 pad)
    constexpr int STG  = 128 * ROWB + 64 * ROWB;   // 27648 bytes per stage
    extern __shared__ __align__(16) char smem[];
    const uint32_t sb = smem_u32(smem);

    const int tid  = threadIdx.x;
    const int lane = tid & 31;
    const int wid  = tid >> 5;
    const int wm   = wid >> 1;               // 0..3
    const int wn   = wid & 1;                // 0..1
    const int bm   = blockIdx.y * 128;
    const int bn   = blockIdx.x * 64;

    const int pr = tid >> 3;                 // piece row   (0..31 per 256-piece group)
    const int pq = tid & 7;                  // piece quarter (0..7) -> 16B each

    float acc[2][4][4];
#pragma unroll
    for (int i = 0; i < 2; i++)
#pragma unroll
        for (int j = 0; j < 4; j++)
#pragma unroll
            for (int l = 0; l < 4; l++) acc[i][j][l] = 0.f;

    const int lrow  = lane & 15;
    const int lkoff = (lane >> 4) * 8;
    const uint32_t a_off = (uint32_t)((wm * 32 + lrow) * ROWB + lkoff * 2);
    const uint32_t b_off = (uint32_t)(128 * ROWB + (wn * 32 + lrow) * ROWB + lkoff * 2);

    auto issue = [&](int c) {
        const int ak = c * 64;
        const int bk = ((c < 7) ? c : c - 7) * 64;
        const uint32_t base = sb + (uint32_t)(c % 3) * STG;
        // A: 128 rows x 128B = 1024 x 16B pieces -> 4 per thread
#pragma unroll
        for (int j = 0; j < 4; j++) {
            int row = pr + 32 * j;
            const fp16* src = A + (size_t)(bm + row) * 896 + ak + pq * 8;
            CP_ASYNC16(base + row * ROWB + pq * 16, src);
        }
        // B: 64 rows x 128B = 512 x 16B pieces -> 2 per thread
#pragma unroll
        for (int j = 0; j < 2; j++) {
            int row = pr + 32 * j;
            const fp16* src = B + (size_t)(bn + row) * 448 + bk + pq * 8;
            CP_ASYNC16(base + 128 * ROWB + row * ROWB + pq * 16, src);
        }
        CP_COMMIT();
    };

    issue(0); issue(1);
    for (int kt = 0; kt < 14; kt++) {
        if (kt < 13) CP_WAIT1(); else CP_WAIT0();
        __syncthreads();
        if (kt + 2 < 14) issue(kt + 2);     // -> buffer (kt-1)%3, reads done pre-barrier

        const uint32_t base = sb + (uint32_t)(kt % 3) * STG;
#pragma unroll
        for (int ks = 0; ks < 4; ks++) {
            uint32_t a0[4], a1[4], b0[4], b1[4];
            LDM4(a0, base + a_off + ks * 32);
            LDM4(a1, base + a_off + 16 * ROWB + ks * 32);
            LDM4(b0, base + b_off + ks * 32);
            LDM4(b1, base + b_off + 16 * ROWB + ks * 32);
            MMA16816(acc[0][0], a0, b0[0], b0[2]);
            MMA16816(acc[0][1], a0, b0[1], b0[3]);
            MMA16816(acc[0][2], a0, b1[0], b1[2]);
            MMA16816(acc[0][3], a0, b1[1], b1[3]);
            MMA16816(acc[1][0], a1, b0[0], b0[2]);
            MMA16816(acc[1][1], a1, b0[1], b0[3]);
            MMA16816(acc[1][2], a1, b1[0], b1[2]);
            MMA16816(acc[1][3], a1, b1[1], b1[3]);
        }
    }

    // ---- epilogue ----
    const int crow = lane >> 2;
    const int ccol = (lane & 3) * 2;
#pragma unroll
    for (int mf = 0; mf < 2; mf++) {
#pragma unroll
        for (int noct = 0; noct < 4; noct++) {
            const int gn = bn + wn * 32 + noct * 8 + ccol;
#pragma unroll
            for (int half = 0; half < 2; half++) {
                const int gm = bm + wm * 32 + mf * 16 + crow + half * 8;
                float v0 = acc[mf][noct][half * 2]     * scale;
                float v1 = acc[mf][noct][half * 2 + 1] * scale;
                if (EPI == 0) {
                    *(float2*)&outf[(size_t)gm * 640 + gn] = make_float2(v0, v1);
                } else if (EPI == 1) {
                    v0 = v0 / (1.f + expf(-v0));
                    v1 = v1 / (1.f + expf(-v1));
                    size_t o = (size_t)gm * 896 + gn;
                    fp16 h0, l0, h1, l1;
                    split2h(v0, &h0, &l0);
                    split2h(v1, &h1, &l1);
                    *(__half2*)&oh[o] = __half2(h0, h1);
                    *(__half2*)&oh[o + 448] = __half2(l0, l1);
                } else {
                    if (gn < 448) {
                        size_t o = (size_t)gm * 896 + gn;
                        __half2 sh = *(const __half2*)&sin_[o];
                        __half2 sl = *(const __half2*)&sin_[o + 448];
                        float s0 = __half2float(sh.x) + __half2float(sl.x);
                        float s1 = __half2float(sh.y) + __half2float(sl.y);
                        fp16 h0, l0, h1, l1;
                        split2h(s0 * v0, &h0, &l0);
                        split2h(s1 * v1, &h1, &l1);
                        *(__half2*)&oh[o] = __half2(h0, h1);
                        *(__half2*)&oh[o + 448] = __half2(l0, l1);
                    } else {
                        *(float2*)&outf[(size_t)gm * 128 + gn - 448] = make_float2(v0, v1);
                    }
                }
            }
        }
    }
}

// ======================= o1 + RMS (4-node unrolled) =======================
__global__ void __launch_bounds__(256)
gate_o1_kernel(const float* __restrict__ x, const float* __restrict__ Wl1,
               const float* __restrict__ g1o, float* __restrict__ out) {
    extern __shared__ float sm[];
    float* Wt  = sm;                    // [128][129]
    float* v1s = sm + 128 * 129;        // 8 nodes x 384
    float* ssq = v1s + 8 * 384;         // 8 nodes x 4 warps

    const int tid = threadIdx.x;
    for (int idx = tid; idx < 128 * 128; idx += 256) {
        int m = idx >> 7, k = idx & 127;
        Wt[k * 129 + m] = Wl1[idx];
    }
    const int h  = tid >> 7;
    const int k  = tid & 127;
    const int w4 = (tid >> 5) & 3;
    const int base = blockIdx.x * 32;
    const float sc = 0.08838834764831845f;  // 1/sqrt(128)

    for (int p = 0; p < 4; p++) {
        __syncthreads();
        const int n0 = base + p * 8;
        for (int idx = tid; idx < 8 * 384; idx += 256) {
            int j = idx / 384;
            int r = idx - j * 384;
            int m = r / 3;
            v1s[idx] = x[(size_t)(n0 + j) * 640 + 256 + r] *
                       g1o[(size_t)(n0 + j) * 128 + m];
        }
        __syncthreads();

        const float* vb = v1s + h * 4 * 384;
        float acc[4][3];
#pragma unroll
        for (int j = 0; j < 4; j++) { acc[j][0] = acc[j][1] = acc[j][2] = 0.f; }
#pragma unroll
        for (int m4 = 0; m4 < 32; m4++) {
            float w0 = Wt[k * 129 + 4 * m4 + 0];
            float w1 = Wt[k * 129 + 4 * m4 + 1];
            float w2 = Wt[k * 129 + 4 * m4 + 2];
            float w3 = Wt[k * 129 + 4 * m4 + 3];
#pragma unroll
            for (int j = 0; j < 4; j++) {
                const float* v = vb + j * 384 + m4 * 12;
                float4 va = *(const float4*)(v);
                float4 vm = *(const float4*)(v + 4);
                float4 vc = *(const float4*)(v + 8);
                acc[j][0] = fmaf(va.x, w0, fmaf(va.w, w1, fmaf(vm.z, w2, fmaf(vc.y, w3, acc[j][0]))));
                acc[j][1] = fmaf(va.y, w0, fmaf(vm.x, w1, fmaf(vm.w, w2, fmaf(vc.z, w3, acc[j][1]))));
                acc[j][2] = fmaf(va.z, w0, fmaf(vm.y, w1, fmaf(vc.x, w2, fmaf(vc.w, w3, acc[j][2]))));
            }
        }
#pragma unroll
        for (int j = 0; j < 4; j++) {
            acc[j][0] *= sc; acc[j][1] *= sc; acc[j][2] *= sc;
            float q = acc[j][0]*acc[j][0] + acc[j][1]*acc[j][1] + acc[j][2]*acc[j][2];
#pragma unroll
            for (int o = 16; o; o >>= 1) q += __shfl_xor_sync(0xffffffffu, q, o);
            if ((tid & 31) == 0) ssq[(h * 4 + j) * 4 + w4] = q;
        }
        __syncthreads();
#pragma unroll
        for (int j = 0; j < 4; j++) {
            int nj = h * 4 + j;
            float tot = ssq[nj * 4] + ssq[nj * 4 + 1] + ssq[nj * 4 + 2] + ssq[nj * 4 + 3];
            float rr = rsqrtf(tot * (1.f / 384.f) + 1e-6f);
            size_t ob = (size_t)(n0 + nj) * 640 + 256 + 3 * k;
            out[ob]     = acc[j][0] * rr;
            out[ob + 1] = acc[j][1] * rr;
            out[ob + 2] = acc[j][2] * rr;
        }
    }
}

// ======================= LayerNorm over out[:, :256] =======================
__global__ void lnorm_kernel(float* __restrict__ out) {
    int n = blockIdx.x * blockDim.y + threadIdx.y;
    float* row = out + (size_t)n * 640;
    int lane = threadIdx.x;
    float v[8];
    float s = 0.f;
#pragma unroll
    for (int j = 0; j < 8; j++) { v[j] = row[lane + 32 * j]; s += v[j]; }
#pragma unroll
    for (int o = 16; o; o >>= 1) s += __shfl_xor_sync(0xffffffffu, s, o);
    float mu = s * (1.f / 256.f);
    float q = 0.f;
#pragma unroll
    for (int j = 0; j < 8; j++) { float d = v[j] - mu; q = fmaf(d, d, q); }
#pragma unroll
    for (int o = 16; o; o >>= 1) q += __shfl_xor_sync(0xffffffffu, q, o);
    float r = rsqrtf(q * (1.f / 256.f) + 1e-6f);
#pragma unroll
    for (int j = 0; j < 8; j++) row[lane + 32 * j] = (v[j] - mu) * r;
}

// ======================= launch =======================
extern "C" void kernel_launch(void* const* d_in, const int* in_sizes, int n_in,
                              void* d_out, int out_size) {
    const float* x   = (const float*)d_in[0];   // [32768, 640]
    const float* W1  = (const float*)d_in[1];   // [448, 448]
    const float* W2  = (const float*)d_in[2];   // [448, 832]
    const float* Wl0 = (const float*)d_in[3];   // [448, 256]
    const float* Wl1 = (const float*)d_in[4];   // [128, 128]
    float* out = (float*)d_out;                 // [32768, 640]

    fp16 *s, *h, *sg, *w1, *w2, *wl0;
    float* g1o;
    cudaGetSymbolAddress((void**)&s,   g_s);
    cudaGetSymbolAddress((void**)&h,   g_h);
    cudaGetSymbolAddress((void**)&sg,  g_sg);
    cudaGetSymbolAddress((void**)&g1o, g_g1o);
    cudaGetSymbolAddress((void**)&w1,  g_w1);
    cudaGetSymbolAddress((void**)&w2,  g_w2);
    cudaGetSymbolAddress((void**)&wl0, g_wl0);

    const float inv_fan = 0.04724555652982141f;  // 1/sqrt(448)
    const int GEMM_SMEM = 3 * 27648;             // 82944

    cudaFuncSetAttribute(mma_gemm<0>, cudaFuncAttributeMaxDynamicSharedMemorySize, GEMM_SMEM);
    cudaFuncSetAttribute(mma_gemm<1>, cudaFuncAttributeMaxDynamicSharedMemorySize, GEMM_SMEM);
    cudaFuncSetAttribute(mma_gemm<2>, cudaFuncAttributeMaxDynamicSharedMemorySize, GEMM_SMEM);

    prep_split_kernel<<<NN, 448>>>(x);
    prep_w_kernel<<<560, 256>>>(W1, W2, Wl0);

    // GEMM1: h = silu(s @ W1 / sqrt(448))   [N=448]
    mma_gemm<1><<<dim3(7, NN / 128), 256, GEMM_SMEM>>>(s, w1, inv_fan, nullptr, h, nullptr);

    // GEMM2: gates; cols<448 -> sg = s*gate, cols>=448 -> g1o   [N=576]
    mma_gemm<2><<<dim3(9, NN / 128), 256, GEMM_SMEM>>>(h, w2, inv_fan, g1o, sg, s);

    // o1 + RMS -> out[:, 256:640]
    int go_smem = (128 * 129 + 8 * 384 + 32) * 4;
    cudaFuncSetAttribute(gate_o1_kernel, cudaFuncAttributeMaxDynamicSharedMemorySize, go_smem);
    gate_o1_kernel<<<NN / 32, 256, go_smem>>>(x, Wl1, g1o, out);

    // GEMM3: o0 = sg @ Wl0 / sqrt(448) -> out[:, :256]   [N=256]
    mma_gemm<0><<<dim3(4, NN / 128), 256, GEMM_SMEM>>>(sg, wl0, inv_fan, out, nullptr, nullptr);

    // LayerNorm over out[:, :256]
    lnorm_kernel<<<NN / 8, dim3(32, 8)>>>(out);
}

// round 12
// speedup vs baseline: 2.5299x; 1.3247x over previous
#include <cuda_runtime.h>
#include <cuda_fp16.h>
#include <cstdint>

#define NN 32768
typedef __half fp16;

// ======================= static scratch (__device__ globals) =======================
// activations: plain fp16, 448 wide
__device__ __align__(16) fp16 g_s [(size_t)NN * 448];
__device__ __align__(16) fp16 g_h [(size_t)NN * 448];
__device__ __align__(16) fp16 g_sg[(size_t)NN * 448];
__device__ __align__(16) float g_g1o[(size_t)NN * 128];
// weights: plain fp16, transposed: W'[n][k]
__device__ __align__(16) fp16 g_w1 [448 * 448];
__device__ __align__(16) fp16 g_w2 [576 * 448];
__device__ __align__(16) fp16 g_wl0[256 * 448];

__device__ __forceinline__ uint32_t smem_u32(const void* p) {
    uint32_t a;
    asm("{ .reg .u64 t; cvta.to.shared.u64 t, %1; cvt.u32.u64 %0, t; }" : "=r"(a) : "l"(p));
    return a;
}

#define CP_ASYNC16(dst_u32, src_ptr) \
    asm volatile("cp.async.cg.shared.global [%0], [%1], 16;" \
                 :: "r"(dst_u32), "l"(src_ptr) : "memory")
#define CP_COMMIT()  asm volatile("cp.async.commit_group;" ::: "memory")
#define CP_WAIT1()   asm volatile("cp.async.wait_group 1;" ::: "memory")
#define CP_WAIT0()   asm volatile("cp.async.wait_group 0;" ::: "memory")

#define LDM4(r, addr) \
    asm volatile("ldmatrix.sync.aligned.m8n8.x4.shared.b16 {%0,%1,%2,%3}, [%4];" \
        : "=r"((r)[0]), "=r"((r)[1]), "=r"((r)[2]), "=r"((r)[3]) : "r"(addr))

#define MMA16816(d, a, b0r, b1r) \
    asm volatile("mma.sync.aligned.m16n8k16.row.col.f32.f16.f16.f32 " \
        "{%0,%1,%2,%3}, {%4,%5,%6,%7}, {%8,%9}, {%0,%1,%2,%3};" \
        : "+f"((d)[0]), "+f"((d)[1]), "+f"((d)[2]), "+f"((d)[3]) \
        : "r"((a)[0]), "r"((a)[1]), "r"((a)[2]), "r"((a)[3]), "r"(b0r), "r"(b1r))

// ======================= prep: x -> s (fp16, 448) =======================
__global__ void prep_split_kernel(const float* __restrict__ x) {
    const float ISQ3 = 0.57735026918962576f;
    const float SQ2  = 1.41421356237309505f;
    int n = blockIdx.x;
    int j = threadIdx.x;
    float val;
    if (j < 256) {
        val = x[(size_t)n * 640 + j];
    } else {
        int jj = j - 256;
        int g = jj / 3;
        int i = jj - 3 * g;
        const float* p = x + (size_t)n * 640 + 256 + 6 * g;
        float ax = p[0], ay = p[1], az = p[2];
        float bx = p[3], by = p[4], bz = p[5];
        if (i == 0)      val = (ax*ax + ay*ay + az*az) * ISQ3;
        else if (i == 1) val = SQ2 * (ax*bx + ay*by + az*bz) * ISQ3;
        else             val = (bx*bx + by*by + bz*bz) * ISQ3;
    }
    g_s[(size_t)n * 448 + j] = __float2half_rn(val);
}

// ======================= prep: transpose + quantize weights =======================
__global__ void prep_w_kernel(const float* __restrict__ W1,
                              const float* __restrict__ W2,
                              const float* __restrict__ Wl0) {
    int idx = blockIdx.x * blockDim.x + threadIdx.x;
    int stride = gridDim.x * blockDim.x;
    const int T1 = 448 * 448, T2 = T1 + 576 * 448, T3 = T2 + 256 * 448;
    for (; idx < T3; idx += stride) {
        if (idx < T1) {
            int n = idx / 448, k = idx - n * 448;
            g_w1[idx] = __float2half_rn(W1[(size_t)k * 448 + n]);
        } else if (idx < T2) {
            int i = idx - T1;
            int n = i / 448, k = i - n * 448;
            g_w2[i] = __float2half_rn(W2[(size_t)k * 832 + n]);
        } else {
            int i = idx - T2;
            int n = i / 448, k = i - n * 448;
            g_wl0[i] = __float2half_rn(Wl0[(size_t)k * 256 + n]);
        }
    }
}

// ======================= mma.sync fp16 GEMM (TN, K = 448) =======================
// C = A @ B^T * scale, fp32 accum. K = 448 = 7 chunks of 64.
// Block 128x64, 8 warps (warp tile 32x32), BK=64, 3-stage cp.async, ONE barrier/iter.
// SMEM rows padded to 144B (odd multiple of 16 -> ldmatrix conflict-free).
// EPI: 0 = fp32 to outf (ld 640); 1 = silu -> oh fp16;
//      2 = col<448: sg = s*gate -> oh ; col>=448: g1o fp32 -> outf (ld 128).
template <int EPI>
__global__ void __launch_bounds__(256)
mma_gemm(const fp16* __restrict__ A, const fp16* __restrict__ B,
         float scale, float* __restrict__ outf, fp16* __restrict__ oh,
         const fp16* __restrict__ sin_) {
    constexpr int ROWB = 144;                 // bytes per SMEM row (128 data + 16 pad)
    constexpr int STG  = 128 * ROWB + 64 * ROWB;   // 27648 bytes per stage
    extern __shared__ __align__(16) char smem[];
    const uint32_t sb = smem_u32(smem);

    const int tid  = threadIdx.x;
    const int lane = tid & 31;
    const int wid  = tid >> 5;
    const int wm   = wid >> 1;               // 0..3
    const int wn   = wid & 1;                // 0..1
    const int bm   = blockIdx.y * 128;
    const int bn   = blockIdx.x * 64;

    const int pr = tid >> 3;                 // piece row (0..31 per 256-piece group)
    const int pq = tid & 7;                  // 16B piece within row

    float acc[2][4][4];
#pragma unroll
    for (int i = 0; i < 2; i++)
#pragma unroll
        for (int j = 0; j < 4; j++)
#pragma unroll
            for (int l = 0; l < 4; l++) acc[i][j][l] = 0.f;

    const int lrow  = lane & 15;
    const int lkoff = (lane >> 4) * 8;
    const uint32_t a_off = (uint32_t)((wm * 32 + lrow) * ROWB + lkoff * 2);
    const uint32_t b_off = (uint32_t)(128 * ROWB + (wn * 32 + lrow) * ROWB + lkoff * 2);

    auto issue = [&](int c) {
        const int k0 = c * 64;
        const uint32_t base = sb + (uint32_t)(c % 3) * STG;
#pragma unroll
        for (int j = 0; j < 4; j++) {
            int row = pr + 32 * j;
            const fp16* src = A + (size_t)(bm + row) * 448 + k0 + pq * 8;
            CP_ASYNC16(base + row * ROWB + pq * 16, src);
        }
#pragma unroll
        for (int j = 0; j < 2; j++) {
            int row = pr + 32 * j;
            const fp16* src = B + (size_t)(bn + row) * 448 + k0 + pq * 8;
            CP_ASYNC16(base + 128 * ROWB + row * ROWB + pq * 16, src);
        }
        CP_COMMIT();
    };

    issue(0); issue(1);
    for (int kt = 0; kt < 7; kt++) {
        if (kt < 6) CP_WAIT1(); else CP_WAIT0();
        __syncthreads();
        if (kt + 2 < 7) issue(kt + 2);      // -> buffer (kt-1)%3, reads done pre-barrier

        const uint32_t base = sb + (uint32_t)(kt % 3) * STG;
#pragma unroll
        for (int ks = 0; ks < 4; ks++) {
            uint32_t a0[4], a1[4], b0[4], b1[4];
            LDM4(a0, base + a_off + ks * 32);
            LDM4(a1, base + a_off + 16 * ROWB + ks * 32);
            LDM4(b0, base + b_off + ks * 32);
            LDM4(b1, base + b_off + 16 * ROWB + ks * 32);
            MMA16816(acc[0][0], a0, b0[0], b0[2]);
            MMA16816(acc[0][1], a0, b0[1], b0[3]);
            MMA16816(acc[0][2], a0, b1[0], b1[2]);
            MMA16816(acc[0][3], a0, b1[1], b1[3]);
            MMA16816(acc[1][0], a1, b0[0], b0[2]);
            MMA16816(acc[1][1], a1, b0[1], b0[3]);
            MMA16816(acc[1][2], a1, b1[0], b1[2]);
            MMA16816(acc[1][3], a1, b1[1], b1[3]);
        }
    }

    // ---- epilogue ----
    const int crow = lane >> 2;
    const int ccol = (lane & 3) * 2;
#pragma unroll
    for (int mf = 0; mf < 2; mf++) {
#pragma unroll
        for (int noct = 0; noct < 4; noct++) {
            const int gn = bn + wn * 32 + noct * 8 + ccol;
#pragma unroll
            for (int half = 0; half < 2; half++) {
                const int gm = bm + wm * 32 + mf * 16 + crow + half * 8;
                float v0 = acc[mf][noct][half * 2]     * scale;
                float v1 = acc[mf][noct][half * 2 + 1] * scale;
                if (EPI == 0) {
                    *(float2*)&outf[(size_t)gm * 640 + gn] = make_float2(v0, v1);
                } else if (EPI == 1) {
                    v0 = v0 / (1.f + expf(-v0));
                    v1 = v1 / (1.f + expf(-v1));
                    *(__half2*)&oh[(size_t)gm * 448 + gn] =
                        __half2(__float2half_rn(v0), __float2half_rn(v1));
                } else {
                    if (gn < 448) {
                        size_t o = (size_t)gm * 448 + gn;
                        __half2 sv = *(const __half2*)&sin_[o];
                        float s0 = __half2float(sv.x);
                        float s1 = __half2float(sv.y);
                        *(__half2*)&oh[o] =
                            __half2(__float2half_rn(s0 * v0), __float2half_rn(s1 * v1));
                    } else {
                        *(float2*)&outf[(size_t)gm * 128 + gn - 448] = make_float2(v0, v1);
                    }
                }
            }
        }
    }
}

// ======================= o1 + RMS (4-node unrolled) =======================
__global__ void __launch_bounds__(256)
gate_o1_kernel(const float* __restrict__ x, const float* __restrict__ Wl1,
               const float* __restrict__ g1o, float* __restrict__ out) {
    extern __shared__ float sm[];
    float* Wt  = sm;                    // [128][129]
    float* v1s = sm + 128 * 129;        // 8 nodes x 384
    float* ssq = v1s + 8 * 384;         // 8 nodes x 4 warps

    const int tid = threadIdx.x;
    for (int idx = tid; idx < 128 * 128; idx += 256) {
        int m = idx >> 7, k = idx & 127;
        Wt[k * 129 + m] = Wl1[idx];
    }
    const int h  = tid >> 7;
    const int k  = tid & 127;
    const int w4 = (tid >> 5) & 3;
    const int base = blockIdx.x * 32;
    const float sc = 0.08838834764831845f;  // 1/sqrt(128)

    for (int p = 0; p < 4; p++) {
        __syncthreads();
        const int n0 = base + p * 8;
        for (int idx = tid; idx < 8 * 384; idx += 256) {
            int j = idx / 384;
            int r = idx - j * 384;
            int m = r / 3;
            v1s[idx] = x[(size_t)(n0 + j) * 640 + 256 + r] *
                       g1o[(size_t)(n0 + j) * 128 + m];
        }
        __syncthreads();

        const float* vb = v1s + h * 4 * 384;
        float acc[4][3];
#pragma unroll
        for (int j = 0; j < 4; j++) { acc[j][0] = acc[j][1] = acc[j][2] = 0.f; }
#pragma unroll
        for (int m4 = 0; m4 < 32; m4++) {
            float w0 = Wt[k * 129 + 4 * m4 + 0];
            float w1 = Wt[k * 129 + 4 * m4 + 1];
            float w2 = Wt[k * 129 + 4 * m4 + 2];
            float w3 = Wt[k * 129 + 4 * m4 + 3];
#pragma unroll
            for (int j = 0; j < 4; j++) {
                const float* v = vb + j * 384 + m4 * 12;
                float4 va = *(const float4*)(v);
                float4 vm = *(const float4*)(v + 4);
                float4 vc = *(const float4*)(v + 8);
                acc[j][0] = fmaf(va.x, w0, fmaf(va.w, w1, fmaf(vm.z, w2, fmaf(vc.y, w3, acc[j][0]))));
                acc[j][1] = fmaf(va.y, w0, fmaf(vm.x, w1, fmaf(vm.w, w2, fmaf(vc.z, w3, acc[j][1]))));
                acc[j][2] = fmaf(va.z, w0, fmaf(vm.y, w1, fmaf(vc.x, w2, fmaf(vc.w, w3, acc[j][2]))));
            }
        }
#pragma unroll
        for (int j = 0; j < 4; j++) {
            acc[j][0] *= sc; acc[j][1] *= sc; acc[j][2] *= sc;
            float q = acc[j][0]*acc[j][0] + acc[j][1]*acc[j][1] + acc[j][2]*acc[j][2];
#pragma unroll
            for (int o = 16; o; o >>= 1) q += __shfl_xor_sync(0xffffffffu, q, o);
            if ((tid & 31) == 0) ssq[(h * 4 + j) * 4 + w4] = q;
        }
        __syncthreads();
#pragma unroll
        for (int j = 0; j < 4; j++) {
            int nj = h * 4 + j;
            float tot = ssq[nj * 4] + ssq[nj * 4 + 1] + ssq[nj * 4 + 2] + ssq[nj * 4 + 3];
            float rr = rsqrtf(tot * (1.f / 384.f) + 1e-6f);
            size_t ob = (size_t)(n0 + nj) * 640 + 256 + 3 * k;
            out[ob]     = acc[j][0] * rr;
            out[ob + 1] = acc[j][1] * rr;
            out[ob + 2] = acc[j][2] * rr;
        }
    }
}

// ======================= LayerNorm over out[:, :256] =======================
__global__ void lnorm_kernel(float* __restrict__ out) {
    int n = blockIdx.x * blockDim.y + threadIdx.y;
    float* row = out + (size_t)n * 640;
    int lane = threadIdx.x;
    float v[8];
    float s = 0.f;
#pragma unroll
    for (int j = 0; j < 8; j++) { v[j] = row[lane + 32 * j]; s += v[j]; }
#pragma unroll
    for (int o = 16; o; o >>= 1) s += __shfl_xor_sync(0xffffffffu, s, o);
    float mu = s * (1.f / 256.f);
    float q = 0.f;
#pragma unroll
    for (int j = 0; j < 8; j++) { float d = v[j] - mu; q = fmaf(d, d, q); }
#pragma unroll
    for (int o = 16; o; o >>= 1) q += __shfl_xor_sync(0xffffffffu, q, o);
    float r = rsqrtf(q * (1.f / 256.f) + 1e-6f);
#pragma unroll
    for (int j = 0; j < 8; j++) row[lane + 32 * j] = (v[j] - mu) * r;
}

// ======================= launch =======================
extern "C" void kernel_launch(void* const* d_in, const int* in_sizes, int n_in,
                              void* d_out, int out_size) {
    const float* x   = (const float*)d_in[0];   // [32768, 640]
    const float* W1  = (const float*)d_in[1];   // [448, 448]
    const float* W2  = (const float*)d_in[2];   // [448, 832]
    const float* Wl0 = (const float*)d_in[3];   // [448, 256]
    const float* Wl1 = (const float*)d_in[4];   // [128, 128]
    float* out = (float*)d_out;                 // [32768, 640]

    fp16 *s, *h, *sg, *w1, *w2, *wl0;
    float* g1o;
    cudaGetSymbolAddress((void**)&s,   g_s);
    cudaGetSymbolAddress((void**)&h,   g_h);
    cudaGetSymbolAddress((void**)&sg,  g_sg);
    cudaGetSymbolAddress((void**)&g1o, g_g1o);
    cudaGetSymbolAddress((void**)&w1,  g_w1);
    cudaGetSymbolAddress((void**)&w2,  g_w2);
    cudaGetSymbolAddress((void**)&wl0, g_wl0);

    const float inv_fan = 0.04724555652982141f;  // 1/sqrt(448)
    const int GEMM_SMEM = 3 * 27648;             // 82944

    cudaFuncSetAttribute(mma_gemm<0>, cudaFuncAttributeMaxDynamicSharedMemorySize, GEMM_SMEM);
    cudaFuncSetAttribute(mma_gemm<1>, cudaFuncAttributeMaxDynamicSharedMemorySize, GEMM_SMEM);
    cudaFuncSetAttribute(mma_gemm<2>, cudaFuncAttributeMaxDynamicSharedMemorySize, GEMM_SMEM);

    prep_split_kernel<<<NN, 448>>>(x);
    prep_w_kernel<<<560, 256>>>(W1, W2, Wl0);

    // GEMM1: h = silu(s @ W1 / sqrt(448))   [N=448]
    mma_gemm<1><<<dim3(7, NN / 128), 256, GEMM_SMEM>>>(s, w1, inv_fan, nullptr, h, nullptr);

    // GEMM2: gates; cols<448 -> sg = s*gate, cols>=448 -> g1o   [N=576]
    mma_gemm<2><<<dim3(9, NN / 128), 256, GEMM_SMEM>>>(h, w2, inv_fan, g1o, sg, s);

    // o1 + RMS -> out[:, 256:640]
    int go_smem = (128 * 129 + 8 * 384 + 32) * 4;
    cudaFuncSetAttribute(gate_o1_kernel, cudaFuncAttributeMaxDynamicSharedMemorySize, go_smem);
    gate_o1_kernel<<<NN / 32, 256, go_smem>>>(x, Wl1, g1o, out);

    // GEMM3: o0 = sg @ Wl0 / sqrt(448) -> out[:, :256]   [N=256]
    mma_gemm<0><<<dim3(4, NN / 128), 256, GEMM_SMEM>>>(sg, wl0, inv_fan, out, nullptr, nullptr);

    // LayerNorm over out[:, :256]
    lnorm_kernel<<<NN / 8, dim3(32, 8)>>>(out);
}

// round 13
// speedup vs baseline: 2.8552x; 1.1286x over previous
#include <cuda_runtime.h>
#include <cuda_fp16.h>
#include <cstdint>

#define NN 32768
typedef __half fp16;

// ======================= static scratch (__device__ globals) =======================
__device__ __align__(16) fp16 g_s [(size_t)NN * 448];
__device__ __align__(16) fp16 g_h [(size_t)NN * 448];
__device__ __align__(16) fp16 g_sg[(size_t)NN * 448];
__device__ __align__(16) float g_g1o[(size_t)NN * 128];
__device__ __align__(16) fp16 g_w1 [448 * 448];
__device__ __align__(16) fp16 g_w2 [576 * 448];
__device__ __align__(16) fp16 g_wl0[256 * 448];

__device__ __forceinline__ uint32_t smem_u32(const void* p) {
    uint32_t a;
    asm("{ .reg .u64 t; cvta.to.shared.u64 t, %1; cvt.u32.u64 %0, t; }" : "=r"(a) : "l"(p));
    return a;
}

#define CP_ASYNC16(dst_u32, src_ptr) \
    asm volatile("cp.async.cg.shared.global [%0], [%1], 16;" \
                 :: "r"(dst_u32), "l"(src_ptr) : "memory")
#define CP_COMMIT()  asm volatile("cp.async.commit_group;" ::: "memory")
#define CP_WAIT1()   asm volatile("cp.async.wait_group 1;" ::: "memory")
#define CP_WAIT0()   asm volatile("cp.async.wait_group 0;" ::: "memory")

#define LDM4(r, addr) \
    asm volatile("ldmatrix.sync.aligned.m8n8.x4.shared.b16 {%0,%1,%2,%3}, [%4];" \
        : "=r"((r)[0]), "=r"((r)[1]), "=r"((r)[2]), "=r"((r)[3]) : "r"(addr))

#define MMA16816(d, a, b0r, b1r) \
    asm volatile("mma.sync.aligned.m16n8k16.row.col.f32.f16.f16.f32 " \
        "{%0,%1,%2,%3}, {%4,%5,%6,%7}, {%8,%9}, {%0,%1,%2,%3};" \
        : "+f"((d)[0]), "+f"((d)[1]), "+f"((d)[2]), "+f"((d)[3]) \
        : "r"((a)[0]), "r"((a)[1]), "r"((a)[2]), "r"((a)[3]), "r"(b0r), "r"(b1r))

// ======================= prep: x -> s (fp16, 448) =======================
__global__ void prep_split_kernel(const float* __restrict__ x) {
    const float ISQ3 = 0.57735026918962576f;
    const float SQ2  = 1.41421356237309505f;
    int n = blockIdx.x;
    int j = threadIdx.x;
    float val;
    if (j < 256) {
        val = x[(size_t)n * 640 + j];
    } else {
        int jj = j - 256;
        int g = jj / 3;
        int i = jj - 3 * g;
        const float* p = x + (size_t)n * 640 + 256 + 6 * g;
        float ax = p[0], ay = p[1], az = p[2];
        float bx = p[3], by = p[4], bz = p[5];
        if (i == 0)      val = (ax*ax + ay*ay + az*az) * ISQ3;
        else if (i == 1) val = SQ2 * (ax*bx + ay*by + az*bz) * ISQ3;
        else             val = (bx*bx + by*by + bz*bz) * ISQ3;
    }
    g_s[(size_t)n * 448 + j] = __float2half_rn(val);
}

// ======================= prep: transpose + quantize weights =======================
__global__ void prep_w_kernel(const float* __restrict__ W1,
                              const float* __restrict__ W2,
                              const float* __restrict__ Wl0) {
    int idx = blockIdx.x * blockDim.x + threadIdx.x;
    int stride = gridDim.x * blockDim.x;
    const int T1 = 448 * 448, T2 = T1 + 576 * 448, T3 = T2 + 256 * 448;
    for (; idx < T3; idx += stride) {
        if (idx < T1) {
            int n = idx / 448, k = idx - n * 448;
            g_w1[idx] = __float2half_rn(W1[(size_t)k * 448 + n]);
        } else if (idx < T2) {
            int i = idx - T1;
            int n = i / 448, k = i - n * 448;
            g_w2[i] = __float2half_rn(W2[(size_t)k * 832 + n]);
        } else {
            int i = idx - T2;
            int n = i / 448, k = i - n * 448;
            g_wl0[i] = __float2half_rn(Wl0[(size_t)k * 256 + n]);
        }
    }
}

// ======================= mma.sync fp16 GEMM (TN, K = 448) =======================
template <int EPI>
__global__ void __launch_bounds__(256)
mma_gemm(const fp16* __restrict__ A, const fp16* __restrict__ B,
         float scale, float* __restrict__ outf, fp16* __restrict__ oh,
         const fp16* __restrict__ sin_) {
    constexpr int ROWB = 144;
    constexpr int STG  = 128 * ROWB + 64 * ROWB;
    extern __shared__ __align__(16) char smem[];
    const uint32_t sb = smem_u32(smem);

    const int tid  = threadIdx.x;
    const int lane = tid & 31;
    const int wid  = tid >> 5;
    const int wm   = wid >> 1;
    const int wn   = wid & 1;
    const int bm   = blockIdx.y * 128;
    const int bn   = blockIdx.x * 64;

    const int pr = tid >> 3;
    const int pq = tid & 7;

    float acc[2][4][4];
#pragma unroll
    for (int i = 0; i < 2; i++)
#pragma unroll
        for (int j = 0; j < 4; j++)
#pragma unroll
            for (int l = 0; l < 4; l++) acc[i][j][l] = 0.f;

    const int lrow  = lane & 15;
    const int lkoff = (lane >> 4) * 8;
    const uint32_t a_off = (uint32_t)((wm * 32 + lrow) * ROWB + lkoff * 2);
    const uint32_t b_off = (uint32_t)(128 * ROWB + (wn * 32 + lrow) * ROWB + lkoff * 2);

    auto issue = [&](int c) {
        const int k0 = c * 64;
        const uint32_t base = sb + (uint32_t)(c % 3) * STG;
#pragma unroll
        for (int j = 0; j < 4; j++) {
            int row = pr + 32 * j;
            const fp16* src = A + (size_t)(bm + row) * 448 + k0 + pq * 8;
            CP_ASYNC16(base + row * ROWB + pq * 16, src);
        }
#pragma unroll
        for (int j = 0; j < 2; j++) {
            int row = pr + 32 * j;
            const fp16* src = B + (size_t)(bn + row) * 448 + k0 + pq * 8;
            CP_ASYNC16(base + 128 * ROWB + row * ROWB + pq * 16, src);
        }
        CP_COMMIT();
    };

    issue(0); issue(1);
    for (int kt = 0; kt < 7; kt++) {
        if (kt < 6) CP_WAIT1(); else CP_WAIT0();
        __syncthreads();
        if (kt + 2 < 7) issue(kt + 2);

        const uint32_t base = sb + (uint32_t)(kt % 3) * STG;
#pragma unroll
        for (int ks = 0; ks < 4; ks++) {
            uint32_t a0[4], a1[4], b0[4], b1[4];
            LDM4(a0, base + a_off + ks * 32);
            LDM4(a1, base + a_off + 16 * ROWB + ks * 32);
            LDM4(b0, base + b_off + ks * 32);
            LDM4(b1, base + b_off + 16 * ROWB + ks * 32);
            MMA16816(acc[0][0], a0, b0[0], b0[2]);
            MMA16816(acc[0][1], a0, b0[1], b0[3]);
            MMA16816(acc[0][2], a0, b1[0], b1[2]);
            MMA16816(acc[0][3], a0, b1[1], b1[3]);
            MMA16816(acc[1][0], a1, b0[0], b0[2]);
            MMA16816(acc[1][1], a1, b0[1], b0[3]);
            MMA16816(acc[1][2], a1, b1[0], b1[2]);
            MMA16816(acc[1][3], a1, b1[1], b1[3]);
        }
    }

    const int crow = lane >> 2;
    const int ccol = (lane & 3) * 2;
#pragma unroll
    for (int mf = 0; mf < 2; mf++) {
#pragma unroll
        for (int noct = 0; noct < 4; noct++) {
            const int gn = bn + wn * 32 + noct * 8 + ccol;
#pragma unroll
            for (int half = 0; half < 2; half++) {
                const int gm = bm + wm * 32 + mf * 16 + crow + half * 8;
                float v0 = acc[mf][noct][half * 2]     * scale;
                float v1 = acc[mf][noct][half * 2 + 1] * scale;
                if (EPI == 0) {
                    *(float2*)&outf[(size_t)gm * 640 + gn] = make_float2(v0, v1);
                } else if (EPI == 1) {
                    v0 = v0 / (1.f + expf(-v0));
                    v1 = v1 / (1.f + expf(-v1));
                    *(__half2*)&oh[(size_t)gm * 448 + gn] =
                        __half2(__float2half_rn(v0), __float2half_rn(v1));
                } else {
                    if (gn < 448) {
                        size_t o = (size_t)gm * 448 + gn;
                        __half2 sv = *(const __half2*)&sin_[o];
                        float s0 = __half2float(sv.x);
                        float s1 = __half2float(sv.y);
                        *(__half2*)&oh[o] =
                            __half2(__float2half_rn(s0 * v0), __float2half_rn(s1 * v1));
                    } else {
                        *(float2*)&outf[(size_t)gm * 128 + gn - 448] = make_float2(v0, v1);
                    }
                }
            }
        }
    }
}

// ======================= tensorized o1 + RMS =======================
// Per block: 64 nodes. C[(3*nl+i), k] = sum_m A[(3nl+i), m] * Wl1[m, k],
// A = v*g1o as fp16 hi/lo (logical K'=256), B = Wl1^T fp16 (reused for both halves).
// 8 warps: 4 in M (48 rows each) x 2 in N (64 cols each).
// SMEM: A [192][528B] (hi at +0, lo at +256 per row), B [128][272B],
//       partial [256]f, rms [64]f.  Epilogue o1 fp32 reuses A buffer (stride 129 f).
__global__ void __launch_bounds__(256)
gate_o1_mma(const float* __restrict__ x, const float* __restrict__ Wl1,
            const float* __restrict__ g1o, float* __restrict__ out) {
    constexpr uint32_t B_OFF = 192 * 528;            // 101376
    constexpr uint32_t P_OFF = B_OFF + 128 * 272;    // 136192
    constexpr uint32_t R_OFF = P_OFF + 256 * 4;      // 137216
    extern __shared__ __align__(16) char smem[];
    const uint32_t sb = smem_u32(smem);

    const int tid  = threadIdx.x;
    const int lane = tid & 31;
    const int wid  = tid >> 5;
    const int wm   = wid >> 1;               // 0..3
    const int wn   = wid & 1;                // 0..1
    const int n0   = blockIdx.x * 64;

    // ---- B = Wl1^T (fp16) ----
    for (int idx = tid; idx < 128 * 128; idx += 256) {
        int m = idx >> 7, k = idx & 127;
        *(fp16*)(smem + B_OFF + k * 272 + m * 2) = __float2half_rn(Wl1[idx]);
    }
    // ---- A = v * g1o, hi/lo split ----
#pragma unroll 4
    for (int j = 0; j < 96; j++) {
        int idx = tid + j * 256;
        int nl = idx / 384;
        int r  = idx - nl * 384;
        int m  = r / 3;
        int i  = r - m * 3;
        float val = x[(size_t)(n0 + nl) * 640 + 256 + r] *
                    g1o[(size_t)(n0 + nl) * 128 + m];
        fp16 h = __float2half_rn(val);
        fp16 l = __float2half_rn(val - __half2float(h));
        int row = 3 * nl + i;
        *(fp16*)(smem + row * 528 + m * 2) = h;
        *(fp16*)(smem + row * 528 + 256 + m * 2) = l;
    }
    __syncthreads();

    // ---- MMA: warp tile 48x64, K' = 256 ----
    const int lrow  = lane & 15;
    const int lkb   = (lane >> 4) * 16;      // 0 or 16 bytes
    float acc[3][8][4];
#pragma unroll
    for (int a = 0; a < 3; a++)
#pragma unroll
        for (int b = 0; b < 8; b++)
#pragma unroll
            for (int c = 0; c < 4; c++) acc[a][b][c] = 0.f;

#pragma unroll
    for (int kk = 0; kk < 16; kk++) {
        const int kbA = (kk & 7) * 32 + (kk >> 3) * 256 + lkb;
        const int kbB = (kk & 7) * 32 + lkb;
        uint32_t a[3][4];
#pragma unroll
        for (int mt = 0; mt < 3; mt++)
            LDM4(a[mt], sb + (wm * 48 + mt * 16 + lrow) * 528 + kbA);
#pragma unroll
        for (int nt = 0; nt < 4; nt++) {
            uint32_t b[4];
            LDM4(b, sb + B_OFF + (wn * 64 + nt * 16 + lrow) * 272 + kbB);
#pragma unroll
            for (int mt = 0; mt < 3; mt++) {
                MMA16816(acc[mt][nt * 2],     a[mt], b[0], b[2]);
                MMA16816(acc[mt][nt * 2 + 1], a[mt], b[1], b[3]);
            }
        }
    }
    __syncthreads();          // all A/B reads done -> safe to overwrite with o1

    // ---- write C (scaled) to SMEM fp32, stride 129 floats ----
    float* o1f = (float*)smem;
    float* Pf  = (float*)(smem + P_OFF);
    float* Rf  = (float*)(smem + R_OFF);
    const float sc = 0.08838834764831845f;   // 1/sqrt(128)
    const int crow = lane >> 2;
    const int ccol = (lane & 3) * 2;
#pragma unroll
    for (int mt = 0; mt < 3; mt++)
#pragma unroll
        for (int nt = 0; nt < 8; nt++)
#pragma unroll
            for (int hf = 0; hf < 2; hf++) {
                int row = wm * 48 + mt * 16 + crow + hf * 8;
                int col = wn * 64 + nt * 8 + ccol;
                o1f[row * 129 + col]     = acc[mt][nt][hf * 2]     * sc;
                o1f[row * 129 + col + 1] = acc[mt][nt][hf * 2 + 1] * sc;
            }
    __syncthreads();

    // ---- per-node ssq (4 threads/node) ----
    {
        int nl = tid >> 2, q = tid & 3;
        float ss = 0.f;
#pragma unroll
        for (int rr = 0; rr < 3; rr++) {
            const float* rp = o1f + (3 * nl + rr) * 129 + q * 32;
#pragma unroll 8
            for (int c = 0; c < 32; c++) ss = fmaf(rp[c], rp[c], ss);
        }
        Pf[tid] = ss;
    }
    __syncthreads();
    if (tid < 64)
        Rf[tid] = rsqrtf((Pf[tid * 4] + Pf[tid * 4 + 1] + Pf[tid * 4 + 2] + Pf[tid * 4 + 3])
                         * (1.f / 384.f) + 1e-6f);
    __syncthreads();

    // ---- write out interleaved ----
#pragma unroll 4
    for (int j = 0; j < 96; j++) {
        int idx = tid + j * 256;
        int nl = idx / 384;
        int r  = idx - nl * 384;
        int k  = r / 3;
        int i  = r - k * 3;
        out[(size_t)(n0 + nl) * 640 + 256 + r] = o1f[(3 * nl + i) * 129 + k] * Rf[nl];
    }
}

// ======================= LayerNorm over out[:, :256] =======================
__global__ void lnorm_kernel(float* __restrict__ out) {
    int n = blockIdx.x * blockDim.y + threadIdx.y;
    float* row = out + (size_t)n * 640;
    int lane = threadIdx.x;
    float v[8];
    float s = 0.f;
#pragma unroll
    for (int j = 0; j < 8; j++) { v[j] = row[lane + 32 * j]; s += v[j]; }
#pragma unroll
    for (int o = 16; o; o >>= 1) s += __shfl_xor_sync(0xffffffffu, s, o);
    float mu = s * (1.f / 256.f);
    float q = 0.f;
#pragma unroll
    for (int j = 0; j < 8; j++) { float d = v[j] - mu; q = fmaf(d, d, q); }
#pragma unroll
    for (int o = 16; o; o >>= 1) q += __shfl_xor_sync(0xffffffffu, q, o);
    float r = rsqrtf(q * (1.f / 256.f) + 1e-6f);
#pragma unroll
    for (int j = 0; j < 8; j++) row[lane + 32 * j] = (v[j] - mu) * r;
}

// ======================= launch =======================
extern "C" void kernel_launch(void* const* d_in, const int* in_sizes, int n_in,
                              void* d_out, int out_size) {
    const float* x   = (const float*)d_in[0];   // [32768, 640]
    const float* W1  = (const float*)d_in[1];   // [448, 448]
    const float* W2  = (const float*)d_in[2];   // [448, 832]
    const float* Wl0 = (const float*)d_in[3];   // [448, 256]
    const float* Wl1 = (const float*)d_in[4];   // [128, 128]
    float* out = (float*)d_out;                 // [32768, 640]

    fp16 *s, *h, *sg, *w1, *w2, *wl0;
    float* g1o;
    cudaGetSymbolAddress((void**)&s,   g_s);
    cudaGetSymbolAddress((void**)&h,   g_h);
    cudaGetSymbolAddress((void**)&sg,  g_sg);
    cudaGetSymbolAddress((void**)&g1o, g_g1o);
    cudaGetSymbolAddress((void**)&w1,  g_w1);
    cudaGetSymbolAddress((void**)&w2,  g_w2);
    cudaGetSymbolAddress((void**)&wl0, g_wl0);

    const float inv_fan = 0.04724555652982141f;  // 1/sqrt(448)
    const int GEMM_SMEM = 3 * 27648;             // 82944
    const int GO_SMEM   = 137216 + 256;          // 137472

    cudaFuncSetAttribute(mma_gemm<0>, cudaFuncAttributeMaxDynamicSharedMemorySize, GEMM_SMEM);
    cudaFuncSetAttribute(mma_gemm<1>, cudaFuncAttributeMaxDynamicSharedMemorySize, GEMM_SMEM);
    cudaFuncSetAttribute(mma_gemm<2>, cudaFuncAttributeMaxDynamicSharedMemorySize, GEMM_SMEM);
    cudaFuncSetAttribute(gate_o1_mma, cudaFuncAttributeMaxDynamicSharedMemorySize, GO_SMEM);

    prep_split_kernel<<<NN, 448>>>(x);
    prep_w_kernel<<<560, 256>>>(W1, W2, Wl0);

    // GEMM1: h = silu(s @ W1 / sqrt(448))   [N=448]
    mma_gemm<1><<<dim3(7, NN / 128), 256, GEMM_SMEM>>>(s, w1, inv_fan, nullptr, h, nullptr);

    // GEMM2: gates; cols<448 -> sg = s*gate, cols>=448 -> g1o   [N=576]
    mma_gemm<2><<<dim3(9, NN / 128), 256, GEMM_SMEM>>>(h, w2, inv_fan, g1o, sg, s);

    // o1 + RMS -> out[:, 256:640]  (tensorized)
    gate_o1_mma<<<NN / 64, 256, GO_SMEM>>>(x, Wl1, g1o, out);

    // GEMM3: o0 = sg @ Wl0 / sqrt(448) -> out[:, :256]   [N=256]
    mma_gemm<0><<<dim3(4, NN / 128), 256, GEMM_SMEM>>>(sg, wl0, inv_fan, out, nullptr, nullptr);

    // LayerNorm over out[:, :256]
    lnorm_kernel<<<NN / 8, dim3(32, 8)>>>(out);
}

// round 15
// speedup vs baseline: 3.0081x; 1.0536x over previous
#include <cuda_runtime.h>
#include <cuda_fp16.h>
#include <cstdint>

#define NN 32768
typedef __half fp16;

// ======================= static scratch (__device__ globals) =======================
__device__ __align__(16) fp16 g_s [(size_t)NN * 448];
__device__ __align__(16) fp16 g_h [(size_t)NN * 448];
__device__ __align__(16) fp16 g_sg[(size_t)NN * 448];
__device__ __align__(16) float g_g1o[(size_t)NN * 128];
// weights transposed W'[n][k], n zero-padded to BN=128 multiples
__device__ __align__(16) fp16 g_w1 [512 * 448];
__device__ __align__(16) fp16 g_w2 [640 * 448];
__device__ __align__(16) fp16 g_wl0[256 * 448];

__device__ __forceinline__ uint32_t smem_u32(const void* p) {
    uint32_t a;
    asm("{ .reg .u64 t; cvta.to.shared.u64 t, %1; cvt.u32.u64 %0, t; }" : "=r"(a) : "l"(p));
    return a;
}

#define CP_ASYNC16(dst_u32, src_ptr) \
    asm volatile("cp.async.cg.shared.global [%0], [%1], 16;" \
                 :: "r"(dst_u32), "l"(src_ptr) : "memory")
#define CP_COMMIT()  asm volatile("cp.async.commit_group;" ::: "memory")
#define CP_WAIT1()   asm volatile("cp.async.wait_group 1;" ::: "memory")
#define CP_WAIT0()   asm volatile("cp.async.wait_group 0;" ::: "memory")

#define LDM4(r, addr) \
    asm volatile("ldmatrix.sync.aligned.m8n8.x4.shared.b16 {%0,%1,%2,%3}, [%4];" \
        : "=r"((r)[0]), "=r"((r)[1]), "=r"((r)[2]), "=r"((r)[3]) : "r"(addr))

#define MMA16816(d, a, b0r, b1r) \
    asm volatile("mma.sync.aligned.m16n8k16.row.col.f32.f16.f16.f32 " \
        "{%0,%1,%2,%3}, {%4,%5,%6,%7}, {%8,%9}, {%0,%1,%2,%3};" \
        : "+f"((d)[0]), "+f"((d)[1]), "+f"((d)[2]), "+f"((d)[3]) \
        : "r"((a)[0]), "r"((a)[1]), "r"((a)[2]), "r"((a)[3]), "r"(b0r), "r"(b1r))

// ======================= prep: x -> s (fp16, 448) =======================
__global__ void prep_split_kernel(const float* __restrict__ x) {
    const float ISQ3 = 0.57735026918962576f;
    const float SQ2  = 1.41421356237309505f;
    int n = blockIdx.x;
    int j = threadIdx.x;
    float val;
    if (j < 256) {
        val = x[(size_t)n * 640 + j];
    } else {
        int jj = j - 256;
        int g = jj / 3;
        int i = jj - 3 * g;
        const float* p = x + (size_t)n * 640 + 256 + 6 * g;
        float ax = p[0], ay = p[1], az = p[2];
        float bx = p[3], by = p[4], bz = p[5];
        if (i == 0)      val = (ax*ax + ay*ay + az*az) * ISQ3;
        else if (i == 1) val = SQ2 * (ax*bx + ay*by + az*bz) * ISQ3;
        else             val = (bx*bx + by*by + bz*bz) * ISQ3;
    }
    g_s[(size_t)n * 448 + j] = __float2half_rn(val);
}

// ======================= prep: tiled transpose + quantize + zero-pad =======================
// dst[n][k] = fp16(src[k][n]) for n<ncols, 0 for ncols<=n<npad. K=448 always.
__global__ void __launch_bounds__(256)
prep_w_kernel(const float* __restrict__ W1, const float* __restrict__ W2,
              const float* __restrict__ Wl0) {
    __shared__ float sm[32][33];
    const float* src; fp16* dst; int ldsrc, ncols, npad;
    if (blockIdx.z == 0)      { src = W1;  dst = g_w1;  ldsrc = 448; ncols = 448; npad = 512; }
    else if (blockIdx.z == 1) { src = W2;  dst = g_w2;  ldsrc = 832; ncols = 576; npad = 640; }
    else                      { src = Wl0; dst = g_wl0; ldsrc = 256; ncols = 256; npad = 256; }
    const int n0 = blockIdx.x * 32;
    const int k0 = blockIdx.y * 32;
    if (n0 >= npad) return;
    const int tx = threadIdx.x, ty = threadIdx.y;   // 32 x 8
#pragma unroll
    for (int rr = 0; rr < 4; rr++) {
        int kk = ty * 4 + rr;
        int n = n0 + tx;
        sm[kk][tx] = (n < ncols) ? src[(size_t)(k0 + kk) * ldsrc + n] : 0.f;
    }
    __syncthreads();
#pragma unroll
    for (int rr = 0; rr < 4; rr++) {
        int n = n0 + ty * 4 + rr;
        if (n < npad)
            dst[(size_t)n * 448 + k0 + tx] = __float2half_rn(sm[tx][ty * 4 + rr]);
    }
}

// ======================= mma.sync fp16 GEMM (TN, K = 448, 128x128 tile) =======================
// C = A @ B^T * scale, fp32 accum. K = 448 = 7 chunks of 64, 3-stage, 1 barrier/iter.
// Block 128x128, 8 warps (4M x 2N, warp tile 32x64). B rows padded (zeros) to grid*128.
// EPI: 0 = fp32 to outf (ld 640); 1 = silu -> oh fp16 (gn<448);
//      2 = gn<448: sg = s*gate -> oh ; 448<=gn<576: g1o fp32 -> outf (ld 128).
template <int EPI>
__global__ void __launch_bounds__(256, 2)
mma_gemm(const fp16* __restrict__ A, const fp16* __restrict__ B,
         float scale, float* __restrict__ outf, fp16* __restrict__ oh,
         const fp16* __restrict__ sin_) {
    constexpr int ROWB = 144;
    constexpr int STG  = 256 * ROWB;           // 36864 per stage (128 A rows + 128 B rows)
    extern __shared__ __align__(16) char smem[];
    const uint32_t sb = smem_u32(smem);

    const int tid  = threadIdx.x;
    const int lane = tid & 31;
    const int wid  = tid >> 5;
    const int wm   = wid >> 1;                 // 0..3
    const int wn   = wid & 1;                  // 0..1
    const int bm   = blockIdx.y * 128;
    const int bn   = blockIdx.x * 128;

    const int pr = tid >> 3;                   // 0..31
    const int pq = tid & 7;

    float acc[2][8][4];
#pragma unroll
    for (int i = 0; i < 2; i++)
#pragma unroll
        for (int j = 0; j < 8; j++)
#pragma unroll
            for (int l = 0; l < 4; l++) acc[i][j][l] = 0.f;

    const int lrow  = lane & 15;
    const int lkoff = (lane >> 4) * 8;
    const uint32_t a_off = (uint32_t)((wm * 32 + lrow) * ROWB + lkoff * 2);
    const uint32_t b_row0 = (uint32_t)(128 * ROWB + (wn * 64 + lrow) * ROWB + lkoff * 2);

    auto issue = [&](int c) {
        const int k0 = c * 64;
        const uint32_t base = sb + (uint32_t)(c % 3) * STG;
#pragma unroll
        for (int j = 0; j < 4; j++) {
            int row = pr + 32 * j;
            const fp16* src = A + (size_t)(bm + row) * 448 + k0 + pq * 8;
            CP_ASYNC16(base + row * ROWB + pq * 16, src);
        }
#pragma unroll
        for (int j = 0; j < 4; j++) {
            int row = pr + 32 * j;
            const fp16* src = B + (size_t)(bn + row) * 448 + k0 + pq * 8;
            CP_ASYNC16(base + 128 * ROWB + row * ROWB + pq * 16, src);
        }
        CP_COMMIT();
    };

    issue(0); issue(1);
    for (int kt = 0; kt < 7; kt++) {
        if (kt < 6) CP_WAIT1(); else CP_WAIT0();
        __syncthreads();
        if (kt + 2 < 7) issue(kt + 2);         // buffer (kt-1)%3, reads done pre-barrier

        const uint32_t base = sb + (uint32_t)(kt % 3) * STG;
#pragma unroll
        for (int ks = 0; ks < 4; ks++) {
            uint32_t a0[4], a1[4];
            LDM4(a0, base + a_off + ks * 32);
            LDM4(a1, base + a_off + 16 * ROWB + ks * 32);
#pragma unroll
            for (int nt = 0; nt < 4; nt++) {
                uint32_t b[4];
                LDM4(b, base + b_row0 + nt * 16 * ROWB + ks * 32);
                MMA16816(acc[0][2 * nt],     a0, b[0], b[2]);
                MMA16816(acc[0][2 * nt + 1], a0, b[1], b[3]);
                MMA16816(acc[1][2 * nt],     a1, b[0], b[2]);
                MMA16816(acc[1][2 * nt + 1], a1, b[1], b[3]);
            }
        }
    }

    // ---- epilogue ----
    const int crow = lane >> 2;
    const int ccol = (lane & 3) * 2;
#pragma unroll
    for (int mf = 0; mf < 2; mf++) {
#pragma unroll
        for (int noct = 0; noct < 8; noct++) {
            const int gn = bn + wn * 64 + noct * 8 + ccol;
#pragma unroll
            for (int half = 0; half < 2; half++) {
                const int gm = bm + wm * 32 + mf * 16 + crow + half * 8;
                float v0 = acc[mf][noct][half * 2]     * scale;
                float v1 = acc[mf][noct][half * 2 + 1] * scale;
                if (EPI == 0) {
                    *(float2*)&outf[(size_t)gm * 640 + gn] = make_float2(v0, v1);
                } else if (EPI == 1) {
                    if (gn < 448) {
                        v0 = v0 / (1.f + expf(-v0));
                        v1 = v1 / (1.f + expf(-v1));
                        *(__half2*)&oh[(size_t)gm * 448 + gn] =
                            __half2(__float2half_rn(v0), __float2half_rn(v1));
                    }
                } else {
                    if (gn < 448) {
                        size_t o = (size_t)gm * 448 + gn;
                        __half2 sv = *(const __half2*)&sin_[o];
                        float s0 = __half2float(sv.x);
                        float s1 = __half2float(sv.y);
                        *(__half2*)&oh[o] =
                            __half2(__float2half_rn(s0 * v0), __float2half_rn(s1 * v1));
                    } else if (gn < 576) {
                        *(float2*)&outf[(size_t)gm * 128 + gn - 448] = make_float2(v0, v1);
                    }
                }
            }
        }
    }
}

// ======================= tensorized o1 + RMS =======================
__global__ void __launch_bounds__(256)
gate_o1_mma(const float* __restrict__ x, const float* __restrict__ Wl1,
            const float* __restrict__ g1o, float* __restrict__ out) {
    constexpr uint32_t B_OFF = 192 * 528;            // 101376
    constexpr uint32_t P_OFF = B_OFF + 128 * 272;    // 136192
    constexpr uint32_t R_OFF = P_OFF + 256 * 4;      // 137216
    extern __shared__ __align__(16) char smem[];
    const uint32_t sb = smem_u32(smem);

    const int tid  = threadIdx.x;
    const int lane = tid & 31;
    const int wid  = tid >> 5;
    const int wm   = wid >> 1;
    const int wn   = wid & 1;
    const int n0   = blockIdx.x * 64;

    for (int idx = tid; idx < 128 * 128; idx += 256) {
        int m = idx >> 7, k = idx & 127;
        *(fp16*)(smem + B_OFF + k * 272 + m * 2) = __float2half_rn(Wl1[idx]);
    }
#pragma unroll 4
    for (int j = 0; j < 96; j++) {
        int idx = tid + j * 256;
        int nl = idx / 384;
        int r  = idx - nl * 384;
        int m  = r / 3;
        int i  = r - m * 3;
        float val = x[(size_t)(n0 + nl) * 640 + 256 + r] *
                    g1o[(size_t)(n0 + nl) * 128 + m];
        fp16 h = __float2half_rn(val);
        fp16 l = __float2half_rn(val - __half2float(h));
        int row = 3 * nl + i;
        *(fp16*)(smem + row * 528 + m * 2) = h;
        *(fp16*)(smem + row * 528 + 256 + m * 2) = l;
    }
    __syncthreads();

    const int lrow  = lane & 15;
    const int lkb   = (lane >> 4) * 16;
    float acc[3][8][4];
#pragma unroll
    for (int a = 0; a < 3; a++)
#pragma unroll
        for (int b = 0; b < 8; b++)
#pragma unroll
            for (int c = 0; c < 4; c++) acc[a][b][c] = 0.f;

#pragma unroll
    for (int kk = 0; kk < 16; kk++) {
        const int kbA = (kk & 7) * 32 + (kk >> 3) * 256 + lkb;
        const int kbB = (kk & 7) * 32 + lkb;
        uint32_t a[3][4];
#pragma unroll
        for (int mt = 0; mt < 3; mt++)
            LDM4(a[mt], sb + (wm * 48 + mt * 16 + lrow) * 528 + kbA);
#pragma unroll
        for (int nt = 0; nt < 4; nt++) {
            uint32_t b[4];
            LDM4(b, sb + B_OFF + (wn * 64 + nt * 16 + lrow) * 272 + kbB);
#pragma unroll
            for (int mt = 0; mt < 3; mt++) {
                MMA16816(acc[mt][nt * 2],     a[mt], b[0], b[2]);
                MMA16816(acc[mt][nt * 2 + 1], a[mt], b[1], b[3]);
            }
        }
    }
    __syncthreads();

    float* o1f = (float*)smem;
    float* Pf  = (float*)(smem + P_OFF);
    float* Rf  = (float*)(smem + R_OFF);
    const float sc = 0.08838834764831845f;
    const int crow = lane >> 2;
    const int ccol = (lane & 3) * 2;
#pragma unroll
    for (int mt = 0; mt < 3; mt++)
#pragma unroll
        for (int nt = 0; nt < 8; nt++)
#pragma unroll
            for (int hf = 0; hf < 2; hf++) {
                int row = wm * 48 + mt * 16 + crow + hf * 8;
                int col = wn * 64 + nt * 8 + ccol;
                o1f[row * 129 + col]     = acc[mt][nt][hf * 2]     * sc;
                o1f[row * 129 + col + 1] = acc[mt][nt][hf * 2 + 1] * sc;
            }
    __syncthreads();

    {
        int nl = tid >> 2, q = tid & 3;
        float ss = 0.f;
#pragma unroll
        for (int rr = 0; rr < 3; rr++) {
            const float* rp = o1f + (3 * nl + rr) * 129 + q * 32;
#pragma unroll 8
            for (int c = 0; c < 32; c++) ss = fmaf(rp[c], rp[c], ss);
        }
        Pf[tid] = ss;
    }
    __syncthreads();
    if (tid < 64)
        Rf[tid] = rsqrtf((Pf[tid * 4] + Pf[tid * 4 + 1] + Pf[tid * 4 + 2] + Pf[tid * 4 + 3])
                         * (1.f / 384.f) + 1e-6f);
    __syncthreads();

#pragma unroll 4
    for (int j = 0; j < 96; j++) {
        int idx = tid + j * 256;
        int nl = idx / 384;
        int r  = idx - nl * 384;
        int k  = r / 3;
        int i  = r - k * 3;
        out[(size_t)(n0 + nl) * 640 + 256 + r] = o1f[(3 * nl + i) * 129 + k] * Rf[nl];
    }
}

// ======================= LayerNorm over out[:, :256] =======================
__global__ void lnorm_kernel(float* __restrict__ out) {
    int n = blockIdx.x * blockDim.y + threadIdx.y;
    float* row = out + (size_t)n * 640;
    int lane = threadIdx.x;
    float v[8];
    float s = 0.f;
#pragma unroll
    for (int j = 0; j < 8; j++) { v[j] = row[lane + 32 * j]; s += v[j]; }
#pragma unroll
    for (int o = 16; o; o >>= 1) s += __shfl_xor_sync(0xffffffffu, s, o);
    float mu = s * (1.f / 256.f);
    float q = 0.f;
#pragma unroll
    for (int j = 0; j < 8; j++) { float d = v[j] - mu; q = fmaf(d, d, q); }
#pragma unroll
    for (int o = 16; o; o >>= 1) q += __shfl_xor_sync(0xffffffffu, q, o);
    float r = rsqrtf(q * (1.f / 256.f) + 1e-6f);
#pragma unroll
    for (int j = 0; j < 8; j++) row[lane + 32 * j] = (v[j] - mu) * r;
}

// ======================= launch =======================
extern "C" void kernel_launch(void* const* d_in, const int* in_sizes, int n_in,
                              void* d_out, int out_size) {
    const float* x   = (const float*)d_in[0];   // [32768, 640]
    const float* W1  = (const float*)d_in[1];   // [448, 448]
    const float* W2  = (const float*)d_in[2];   // [448, 832]
    const float* Wl0 = (const float*)d_in[3];   // [448, 256]
    const float* Wl1 = (const float*)d_in[4];   // [128, 128]
    float* out = (float*)d_out;                 // [32768, 640]

    fp16 *s, *h, *sg, *w1, *w2, *wl0;
    float* g1o;
    cudaGetSymbolAddress((void**)&s,   g_s);
    cudaGetSymbolAddress((void**)&h,   g_h);
    cudaGetSymbolAddress((void**)&sg,  g_sg);
    cudaGetSymbolAddress((void**)&g1o, g_g1o);
    cudaGetSymbolAddress((void**)&w1,  g_w1);
    cudaGetSymbolAddress((void**)&w2,  g_w2);
    cudaGetSymbolAddress((void**)&wl0, g_wl0);

    const float inv_fan = 0.04724555652982141f;  // 1/sqrt(448)
    const int GEMM_SMEM = 3 * 36864;             // 110592
    const int GO_SMEM   = 137216 + 256;          // 137472

    cudaFuncSetAttribute(mma_gemm<0>, cudaFuncAttributeMaxDynamicSharedMemorySize, GEMM_SMEM);
    cudaFuncSetAttribute(mma_gemm<1>, cudaFuncAttributeMaxDynamicSharedMemorySize, GEMM_SMEM);
    cudaFuncSetAttribute(mma_gemm<2>, cudaFuncAttributeMaxDynamicSharedMemorySize, GEMM_SMEM);
    cudaFuncSetAttribute(gate_o1_mma, cudaFuncAttributeMaxDynamicSharedMemorySize, GO_SMEM);

    prep_split_kernel<<<NN, 448>>>(x);
    prep_w_kernel<<<dim3(20, 14, 3), dim3(32, 8)>>>(W1, W2, Wl0);

    // GEMM1: h = silu(s @ W1 / sqrt(448))   [N=448, padded 512]
    mma_gemm<1><<<dim3(4, NN / 128), 256, GEMM_SMEM>>>(s, w1, inv_fan, nullptr, h, nullptr);

    // GEMM2: gates; gn<448 -> sg = s*gate, 448<=gn<576 -> g1o   [N=576, padded 640]
    mma_gemm<2><<<dim3(5, NN / 128), 256, GEMM_SMEM>>>(h, w2, inv_fan, g1o, sg, s);

    // o1 + RMS -> out[:, 256:640]  (tensorized)
    gate_o1_mma<<<NN / 64, 256, GO_SMEM>>>(x, Wl1, g1o, out);

    // GEMM3: o0 = sg @ Wl0 / sqrt(448) -> out[:, :256]   [N=256 exact]
    mma_gemm<0><<<dim3(2, NN / 128), 256, GEMM_SMEM>>>(sg, wl0, inv_fan, out, nullptr, nullptr);

    // LayerNorm over out[:, :256]
    lnorm_kernel<<<NN / 8, dim3(32, 8)>>>(out);
}

// round 16
// speedup vs baseline: 3.1347x; 1.0421x over previous
#include <cuda_runtime.h>
#include <cuda_fp16.h>
#include <cstdint>

#define NN 32768
typedef __half fp16;

// ======================= static scratch (__device__ globals) =======================
__device__ __align__(16) fp16 g_s [(size_t)NN * 448];
__device__ __align__(16) fp16 g_h [(size_t)NN * 448];
__device__ __align__(16) fp16 g_sg[(size_t)NN * 448];
__device__ __align__(16) float g_g1o[(size_t)NN * 128];
// weights transposed W'[n][k], n zero-padded to BN=128 multiples
__device__ __align__(16) fp16 g_w1 [512 * 448];
__device__ __align__(16) fp16 g_w2 [640 * 448];
__device__ __align__(16) fp16 g_wl0[256 * 448];

__device__ __forceinline__ uint32_t smem_u32(const void* p) {
    uint32_t a;
    asm("{ .reg .u64 t; cvta.to.shared.u64 t, %1; cvt.u32.u64 %0, t; }" : "=r"(a) : "l"(p));
    return a;
}

#define CP_ASYNC16(dst_u32, src_ptr) \
    asm volatile("cp.async.cg.shared.global [%0], [%1], 16;" \
                 :: "r"(dst_u32), "l"(src_ptr) : "memory")
#define CP_COMMIT()  asm volatile("cp.async.commit_group;" ::: "memory")
#define CP_WAIT1()   asm volatile("cp.async.wait_group 1;" ::: "memory")
#define CP_WAIT0()   asm volatile("cp.async.wait_group 0;" ::: "memory")

#define LDM4(r, addr) \
    asm volatile("ldmatrix.sync.aligned.m8n8.x4.shared.b16 {%0,%1,%2,%3}, [%4];" \
        : "=r"((r)[0]), "=r"((r)[1]), "=r"((r)[2]), "=r"((r)[3]) : "r"(addr))

#define MMA16816(d, a, b0r, b1r) \
    asm volatile("mma.sync.aligned.m16n8k16.row.col.f32.f16.f16.f32 " \
        "{%0,%1,%2,%3}, {%4,%5,%6,%7}, {%8,%9}, {%0,%1,%2,%3};" \
        : "+f"((d)[0]), "+f"((d)[1]), "+f"((d)[2]), "+f"((d)[3]) \
        : "r"((a)[0]), "r"((a)[1]), "r"((a)[2]), "r"((a)[3]), "r"(b0r), "r"(b1r))

// ======================= prep: x -> s (fp16, 448) =======================
__global__ void prep_split_kernel(const float* __restrict__ x) {
    const float ISQ3 = 0.57735026918962576f;
    const float SQ2  = 1.41421356237309505f;
    int n = blockIdx.x;
    int j = threadIdx.x;
    float val;
    if (j < 256) {
        val = x[(size_t)n * 640 + j];
    } else {
        int jj = j - 256;
        int g = jj / 3;
        int i = jj - 3 * g;
        const float* p = x + (size_t)n * 640 + 256 + 6 * g;
        float ax = p[0], ay = p[1], az = p[2];
        float bx = p[3], by = p[4], bz = p[5];
        if (i == 0)      val = (ax*ax + ay*ay + az*az) * ISQ3;
        else if (i == 1) val = SQ2 * (ax*bx + ay*by + az*bz) * ISQ3;
        else             val = (bx*bx + by*by + bz*bz) * ISQ3;
    }
    g_s[(size_t)n * 448 + j] = __float2half_rn(val);
}

// ======================= prep: tiled transpose + quantize + zero-pad =======================
__global__ void __launch_bounds__(256)
prep_w_kernel(const float* __restrict__ W1, const float* __restrict__ W2,
              const float* __restrict__ Wl0) {
    __shared__ float sm[32][33];
    const float* src; fp16* dst; int ldsrc, ncols, npad;
    if (blockIdx.z == 0)      { src = W1;  dst = g_w1;  ldsrc = 448; ncols = 448; npad = 512; }
    else if (blockIdx.z == 1) { src = W2;  dst = g_w2;  ldsrc = 832; ncols = 576; npad = 640; }
    else                      { src = Wl0; dst = g_wl0; ldsrc = 256; ncols = 256; npad = 256; }
    const int n0 = blockIdx.x * 32;
    const int k0 = blockIdx.y * 32;
    if (n0 >= npad) return;
    const int tx = threadIdx.x, ty = threadIdx.y;   // 32 x 8
#pragma unroll
    for (int rr = 0; rr < 4; rr++) {
        int kk = ty * 4 + rr;
        int n = n0 + tx;
        sm[kk][tx] = (n < ncols) ? src[(size_t)(k0 + kk) * ldsrc + n] : 0.f;
    }
    __syncthreads();
#pragma unroll
    for (int rr = 0; rr < 4; rr++) {
        int n = n0 + ty * 4 + rr;
        if (n < npad)
            dst[(size_t)n * 448 + k0 + tx] = __float2half_rn(sm[tx][ty * 4 + rr]);
    }
}

// ======================= mma.sync fp16 GEMM (TN, K=448, 128x128 tile) =======================
// EPI: 1 = silu -> oh fp16 (gn<448);
//      2 = gn<448: sg = s*gate -> oh ; 448<=gn<576: g1o fp32 -> outf (ld 128).
template <int EPI>
__global__ void __launch_bounds__(256, 2)
mma_gemm(const fp16* __restrict__ A, const fp16* __restrict__ B,
         float scale, float* __restrict__ outf, fp16* __restrict__ oh,
         const fp16* __restrict__ sin_) {
    constexpr int ROWB = 144;
    constexpr int STG  = 256 * ROWB;
    extern __shared__ __align__(16) char smem[];
    const uint32_t sb = smem_u32(smem);

    const int tid  = threadIdx.x;
    const int lane = tid & 31;
    const int wid  = tid >> 5;
    const int wm   = wid >> 1;
    const int wn   = wid & 1;
    const int bm   = blockIdx.y * 128;
    const int bn   = blockIdx.x * 128;

    const int pr = tid >> 3;
    const int pq = tid & 7;

    float acc[2][8][4];
#pragma unroll
    for (int i = 0; i < 2; i++)
#pragma unroll
        for (int j = 0; j < 8; j++)
#pragma unroll
            for (int l = 0; l < 4; l++) acc[i][j][l] = 0.f;

    const int lrow  = lane & 15;
    const int lkoff = (lane >> 4) * 8;
    const uint32_t a_off = (uint32_t)((wm * 32 + lrow) * ROWB + lkoff * 2);
    const uint32_t b_row0 = (uint32_t)(128 * ROWB + (wn * 64 + lrow) * ROWB + lkoff * 2);

    auto issue = [&](int c) {
        const int k0 = c * 64;
        const uint32_t base = sb + (uint32_t)(c % 3) * STG;
#pragma unroll
        for (int j = 0; j < 4; j++) {
            int row = pr + 32 * j;
            const fp16* src = A + (size_t)(bm + row) * 448 + k0 + pq * 8;
            CP_ASYNC16(base + row * ROWB + pq * 16, src);
        }
#pragma unroll
        for (int j = 0; j < 4; j++) {
            int row = pr + 32 * j;
            const fp16* src = B + (size_t)(bn + row) * 448 + k0 + pq * 8;
            CP_ASYNC16(base + 128 * ROWB + row * ROWB + pq * 16, src);
        }
        CP_COMMIT();
    };

    issue(0); issue(1);
    for (int kt = 0; kt < 7; kt++) {
        if (kt < 6) CP_WAIT1(); else CP_WAIT0();
        __syncthreads();
        if (kt + 2 < 7) issue(kt + 2);

        const uint32_t base = sb + (uint32_t)(kt % 3) * STG;
#pragma unroll
        for (int ks = 0; ks < 4; ks++) {
            uint32_t a0[4], a1[4];
            LDM4(a0, base + a_off + ks * 32);
            LDM4(a1, base + a_off + 16 * ROWB + ks * 32);
#pragma unroll
            for (int nt = 0; nt < 4; nt++) {
                uint32_t b[4];
                LDM4(b, base + b_row0 + nt * 16 * ROWB + ks * 32);
                MMA16816(acc[0][2 * nt],     a0, b[0], b[2]);
                MMA16816(acc[0][2 * nt + 1], a0, b[1], b[3]);
                MMA16816(acc[1][2 * nt],     a1, b[0], b[2]);
                MMA16816(acc[1][2 * nt + 1], a1, b[1], b[3]);
            }
        }
    }

    const int crow = lane >> 2;
    const int ccol = (lane & 3) * 2;
#pragma unroll
    for (int mf = 0; mf < 2; mf++) {
#pragma unroll
        for (int noct = 0; noct < 8; noct++) {
            const int gn = bn + wn * 64 + noct * 8 + ccol;
#pragma unroll
            for (int half = 0; half < 2; half++) {
                const int gm = bm + wm * 32 + mf * 16 + crow + half * 8;
                float v0 = acc[mf][noct][half * 2]     * scale;
                float v1 = acc[mf][noct][half * 2 + 1] * scale;
                if (EPI == 1) {
                    if (gn < 448) {
                        v0 = v0 / (1.f + expf(-v0));
                        v1 = v1 / (1.f + expf(-v1));
                        *(__half2*)&oh[(size_t)gm * 448 + gn] =
                            __half2(__float2half_rn(v0), __float2half_rn(v1));
                    }
                } else {
                    if (gn < 448) {
                        size_t o = (size_t)gm * 448 + gn;
                        __half2 sv = *(const __half2*)&sin_[o];
                        float s0 = __half2float(sv.x);
                        float s1 = __half2float(sv.y);
                        *(__half2*)&oh[o] =
                            __half2(__float2half_rn(s0 * v0), __float2half_rn(s1 * v1));
                    } else if (gn < 576) {
                        *(float2*)&outf[(size_t)gm * 128 + gn - 448] = make_float2(v0, v1);
                    }
                }
            }
        }
    }
}

// ======================= GEMM3 + fused LayerNorm =======================
// o0 = sg @ Wl0^T / sqrt(448), then per-row LayerNorm(256) -> out[:, :256].
// Block = 128 rows x ALL 256 cols. 512 threads, 16 warps (4M x 4N), warp 32x64.
// 2-stage cp.async. Row stats via quad-shuffle + smem atomics.
__global__ void __launch_bounds__(512)
gemm3_ln(const fp16* __restrict__ A, const fp16* __restrict__ B,
         float scale, float* __restrict__ outf) {
    constexpr int ROWB = 144;
    constexpr int STG  = (128 + 256) * ROWB;   // 55296 per stage
    extern __shared__ __align__(16) char smem[];
    const uint32_t sb = smem_u32(smem);
    float* rs = (float*)(smem + 2 * STG);      // [128] row sums
    float* rq = rs + 128;                      // [128] row sumsq

    const int tid  = threadIdx.x;
    const int lane = tid & 31;
    const int wid  = tid >> 5;
    const int wm   = wid >> 2;                 // 0..3
    const int wn   = wid & 3;                  // 0..3
    const int bm   = blockIdx.x * 128;

    if (tid < 256) ((float*)(smem + 2 * STG))[tid] = 0.f;

    const int pr = tid >> 3;                   // 0..63
    const int pq = tid & 7;

    float acc[2][8][4];
#pragma unroll
    for (int i = 0; i < 2; i++)
#pragma unroll
        for (int j = 0; j < 8; j++)
#pragma unroll
            for (int l = 0; l < 4; l++) acc[i][j][l] = 0.f;

    const int lrow  = lane & 15;
    const int lkoff = (lane >> 4) * 8;
    const uint32_t a_off = (uint32_t)((wm * 32 + lrow) * ROWB + lkoff * 2);
    const uint32_t b_row0 = (uint32_t)(128 * ROWB + (wn * 64 + lrow) * ROWB + lkoff * 2);

    auto issue = [&](int c) {
        const int k0 = c * 64;
        const uint32_t base = sb + (uint32_t)(c & 1) * STG;
#pragma unroll
        for (int j = 0; j < 2; j++) {
            int row = pr + 64 * j;
            const fp16* src = A + (size_t)(bm + row) * 448 + k0 + pq * 8;
            CP_ASYNC16(base + row * ROWB + pq * 16, src);
        }
#pragma unroll
        for (int j = 0; j < 4; j++) {
            int row = pr + 64 * j;
            const fp16* src = B + (size_t)row * 448 + k0 + pq * 8;
            CP_ASYNC16(base + 128 * ROWB + row * ROWB + pq * 16, src);
        }
        CP_COMMIT();
    };

    issue(0);
    for (int kt = 0; kt < 7; kt++) {
        if (kt < 6) { issue(kt + 1); CP_WAIT1(); }
        else        { CP_WAIT0(); }
        __syncthreads();

        const uint32_t base = sb + (uint32_t)(kt & 1) * STG;
#pragma unroll
        for (int ks = 0; ks < 4; ks++) {
            uint32_t a0[4], a1[4];
            LDM4(a0, base + a_off + ks * 32);
            LDM4(a1, base + a_off + 16 * ROWB + ks * 32);
#pragma unroll
            for (int nt = 0; nt < 4; nt++) {
                uint32_t b[4];
                LDM4(b, base + b_row0 + nt * 16 * ROWB + ks * 32);
                MMA16816(acc[0][2 * nt],     a0, b[0], b[2]);
                MMA16816(acc[0][2 * nt + 1], a0, b[1], b[3]);
                MMA16816(acc[1][2 * nt],     a1, b[0], b[2]);
                MMA16816(acc[1][2 * nt + 1], a1, b[1], b[3]);
            }
        }
        __syncthreads();     // stage reads done before next issue overwrites it
    }

    // ---- row sums (this warp covers 64 of the row's 256 cols) ----
    const int crow = lane >> 2;
    const int ccol = (lane & 3) * 2;
#pragma unroll
    for (int mf = 0; mf < 2; mf++)
#pragma unroll
        for (int half = 0; half < 2; half++) {
            float s = 0.f, q = 0.f;
#pragma unroll
            for (int noct = 0; noct < 8; noct++) {
                float v0 = acc[mf][noct][half * 2]     * scale;
                float v1 = acc[mf][noct][half * 2 + 1] * scale;
                s += v0 + v1;
                q = fmaf(v0, v0, fmaf(v1, v1, q));
            }
            s += __shfl_xor_sync(0xffffffffu, s, 1);
            s += __shfl_xor_sync(0xffffffffu, s, 2);
            q += __shfl_xor_sync(0xffffffffu, q, 1);
            q += __shfl_xor_sync(0xffffffffu, q, 2);
            if ((lane & 3) == 0) {
                int row = wm * 32 + mf * 16 + crow + half * 8;
                atomicAdd(&rs[row], s);
                atomicAdd(&rq[row], q);
            }
        }
    __syncthreads();

    // ---- normalize + write ----
#pragma unroll
    for (int mf = 0; mf < 2; mf++)
#pragma unroll
        for (int half = 0; half < 2; half++) {
            const int row = wm * 32 + mf * 16 + crow + half * 8;
            const float mean = rs[row] * (1.f / 256.f);
            float var = rq[row] * (1.f / 256.f) - mean * mean;
            const float ri = rsqrtf(var + 1e-6f);
            const int gm = bm + row;
#pragma unroll
            for (int noct = 0; noct < 8; noct++) {
                const int gn = wn * 64 + noct * 8 + ccol;
                float v0 = (acc[mf][noct][half * 2]     * scale - mean) * ri;
                float v1 = (acc[mf][noct][half * 2 + 1] * scale - mean) * ri;
                *(float2*)&outf[(size_t)gm * 640 + gn] = make_float2(v0, v1);
            }
        }
}

// ======================= tensorized o1 + RMS (plain fp16, K=128) =======================
__global__ void __launch_bounds__(256)
gate_o1_mma(const float* __restrict__ x, const float* __restrict__ Wl1,
            const float* __restrict__ g1o, float* __restrict__ out) {
    constexpr int AROW = 272;                        // 256B data + 16 pad
    constexpr uint32_t B_OFF = 192 * AROW;           // 52224
    constexpr uint32_t P_OFF = 99072;                // after o1f overlay (192*129*4)
    constexpr uint32_t R_OFF = P_OFF + 256 * 4;
    extern __shared__ __align__(16) char smem[];
    const uint32_t sb = smem_u32(smem);

    const int tid  = threadIdx.x;
    const int lane = tid & 31;
    const int wid  = tid >> 5;
    const int wm   = wid >> 1;
    const int wn   = wid & 1;
    const int n0   = blockIdx.x * 64;

    for (int idx = tid; idx < 128 * 128; idx += 256) {
        int m = idx >> 7, k = idx & 127;
        *(fp16*)(smem + B_OFF + k * AROW + m * 2) = __float2half_rn(Wl1[idx]);
    }
#pragma unroll 4
    for (int j = 0; j < 96; j++) {
        int idx = tid + j * 256;
        int nl = idx / 384;
        int r  = idx - nl * 384;
        int m  = r / 3;
        int i  = r - m * 3;
        float val = x[(size_t)(n0 + nl) * 640 + 256 + r] *
                    g1o[(size_t)(n0 + nl) * 128 + m];
        *(fp16*)(smem + (3 * nl + i) * AROW + m * 2) = __float2half_rn(val);
    }
    __syncthreads();

    const int lrow  = lane & 15;
    const int lkb   = (lane >> 4) * 16;
    float acc[3][8][4];
#pragma unroll
    for (int a = 0; a < 3; a++)
#pragma unroll
        for (int b = 0; b < 8; b++)
#pragma unroll
            for (int c = 0; c < 4; c++) acc[a][b][c] = 0.f;

#pragma unroll
    for (int kk = 0; kk < 8; kk++) {
        const int kb = kk * 32 + lkb;
        uint32_t a[3][4];
#pragma unroll
        for (int mt = 0; mt < 3; mt++)
            LDM4(a[mt], sb + (wm * 48 + mt * 16 + lrow) * AROW + kb);
#pragma unroll
        for (int nt = 0; nt < 4; nt++) {
            uint32_t b[4];
            LDM4(b, sb + B_OFF + (wn * 64 + nt * 16 + lrow) * AROW + kb);
#pragma unroll
            for (int mt = 0; mt < 3; mt++) {
                MMA16816(acc[mt][nt * 2],     a[mt], b[0], b[2]);
                MMA16816(acc[mt][nt * 2 + 1], a[mt], b[1], b[3]);
            }
        }
    }
    __syncthreads();

    float* o1f = (float*)smem;
    float* Pf  = (float*)(smem + P_OFF);
    float* Rf  = (float*)(smem + R_OFF);
    const float sc = 0.08838834764831845f;
    const int crow = lane >> 2;
    const int ccol = (lane & 3) * 2;
#pragma unroll
    for (int mt = 0; mt < 3; mt++)
#pragma unroll
        for (int nt = 0; nt < 8; nt++)
#pragma unroll
            for (int hf = 0; hf < 2; hf++) {
                int row = wm * 48 + mt * 16 + crow + hf * 8;
                int col = wn * 64 + nt * 8 + ccol;
                o1f[row * 129 + col]     = acc[mt][nt][hf * 2]     * sc;
                o1f[row * 129 + col + 1] = acc[mt][nt][hf * 2 + 1] * sc;
            }
    __syncthreads();

    {
        int nl = tid >> 2, q = tid & 3;
        float ss = 0.f;
#pragma unroll
        for (int rr = 0; rr < 3; rr++) {
            const float* rp = o1f + (3 * nl + rr) * 129 + q * 32;
#pragma unroll 8
            for (int c = 0; c < 32; c++) ss = fmaf(rp[c], rp[c], ss);
        }
        Pf[tid] = ss;
    }
    __syncthreads();
    if (tid < 64)
        Rf[tid] = rsqrtf((Pf[tid * 4] + Pf[tid * 4 + 1] + Pf[tid * 4 + 2] + Pf[tid * 4 + 3])
                         * (1.f / 384.f) + 1e-6f);
    __syncthreads();

#pragma unroll 4
    for (int j = 0; j < 96; j++) {
        int idx = tid + j * 256;
        int nl = idx / 384;
        int r  = idx - nl * 384;
        int k  = r / 3;
        int i  = r - k * 3;
        out[(size_t)(n0 + nl) * 640 + 256 + r] = o1f[(3 * nl + i) * 129 + k] * Rf[nl];
    }
}

// ======================= launch =======================
extern "C" void kernel_launch(void* const* d_in, const int* in_sizes, int n_in,
                              void* d_out, int out_size) {
    const float* x   = (const float*)d_in[0];   // [32768, 640]
    const float* W1  = (const float*)d_in[1];   // [448, 448]
    const float* W2  = (const float*)d_in[2];   // [448, 832]
    const float* Wl0 = (const float*)d_in[3];   // [448, 256]
    const float* Wl1 = (const float*)d_in[4];   // [128, 128]
    float* out = (float*)d_out;                 // [32768, 640]

    fp16 *s, *h, *sg, *w1, *w2, *wl0;
    float* g1o;
    cudaGetSymbolAddress((void**)&s,   g_s);
    cudaGetSymbolAddress((void**)&h,   g_h);
    cudaGetSymbolAddress((void**)&sg,  g_sg);
    cudaGetSymbolAddress((void**)&g1o, g_g1o);
    cudaGetSymbolAddress((void**)&w1,  g_w1);
    cudaGetSymbolAddress((void**)&w2,  g_w2);
    cudaGetSymbolAddress((void**)&wl0, g_wl0);

    const float inv_fan = 0.04724555652982141f;  // 1/sqrt(448)
    const int GEMM_SMEM = 3 * 36864;             // 110592
    const int G3_SMEM   = 2 * 55296 + 1024;      // 111616
    const int GO_SMEM   = 99072 + 1024 + 256;    // 100352

    cudaFuncSetAttribute(mma_gemm<1>, cudaFuncAttributeMaxDynamicSharedMemorySize, GEMM_SMEM);
    cudaFuncSetAttribute(mma_gemm<2>, cudaFuncAttributeMaxDynamicSharedMemorySize, GEMM_SMEM);
    cudaFuncSetAttribute(gemm3_ln,    cudaFuncAttributeMaxDynamicSharedMemorySize, G3_SMEM);
    cudaFuncSetAttribute(gate_o1_mma, cudaFuncAttributeMaxDynamicSharedMemorySize, GO_SMEM);

    prep_split_kernel<<<NN, 448>>>(x);
    prep_w_kernel<<<dim3(20, 14, 3), dim3(32, 8)>>>(W1, W2, Wl0);

    // GEMM1: h = silu(s @ W1 / sqrt(448))   [N=448, padded 512]
    mma_gemm<1><<<dim3(4, NN / 128), 256, GEMM_SMEM>>>(s, w1, inv_fan, nullptr, h, nullptr);

    // GEMM2: gates; gn<448 -> sg = s*gate, 448<=gn<576 -> g1o   [N=576, padded 640]
    mma_gemm<2><<<dim3(5, NN / 128), 256, GEMM_SMEM>>>(h, w2, inv_fan, g1o, sg, s);

    // o1 + RMS -> out[:, 256:640]  (tensorized, plain fp16)
    gate_o1_mma<<<NN / 64, 256, GO_SMEM>>>(x, Wl1, g1o, out);

    // GEMM3 + LayerNorm -> out[:, :256]
    gemm3_ln<<<NN / 128, 512, G3_SMEM>>>(sg, wl0, inv_fan, out);
}